// round 1
// baseline (speedup 1.0000x reference)
#include <cuda_runtime.h>
#include <cuda_bf16.h>
#include <cstdint>
#include <cstddef>

// Problem constants
#define T_   256
#define B_   64
#define DIN_ 512
#define H_   1024
#define CH_  2048          // 2*H
#define G_   6144          // 3*CH
#define DOUT_ 512
#define MB_  (T_*B_)       // 16384

// ---------------- scratch (device globals; no allocations allowed) ----------
__device__ float g_xe[(size_t)MB_ * H_];        // 16384 x 1024   (64 MB)
__device__ float g_gx[(size_t)MB_ * G_];        // 16384 x 6144   (402 MB)
__device__ float g_gh[(size_t)B_ * G_];         // 64 x 6144
__device__ float g_h0[(size_t)B_ * CH_];        // zeros (.bss, never written)

// ---------------- packed fp32x2 helpers (FFMA2) ------------------------------
__device__ __forceinline__ unsigned long long pack2(float x, float y) {
    unsigned long long r;
    asm("mov.b64 %0, {%1, %2};" : "=l"(r) : "f"(x), "f"(y));
    return r;
}
__device__ __forceinline__ void fma2(unsigned long long& a,
                                     unsigned long long x,
                                     unsigned long long y) {
    asm("fma.rn.f32x2 %0, %1, %2, %0;" : "+l"(a) : "l"(x), "l"(y));
}
__device__ __forceinline__ float2 unpack2(unsigned long long v) {
    float2 f;
    asm("mov.b64 {%0, %1}, %2;" : "=f"(f.x), "=f"(f.y) : "l"(v));
    return f;
}

// ---------------- activations ------------------------------------------------
__device__ __forceinline__ float act_elu(float v) {
    return v > 0.0f ? v : expm1f(v);
}
__device__ __forceinline__ float act_softplus01(float v) {
    // stable softplus + 0.1
    return fmaxf(v, 0.0f) + log1pf(expf(-fabsf(v))) + 0.1f;
}

// ---------------- generic GEMM: C[M,N] = act(A[M,K] * W[N,K]^T + bias[N]) ----
// BM = BN = 64, BK = 16, 256 threads, per-thread 4m x 4n micro-tile.
// All dims assumed divisible: M%64==0, N%64==0, K%16==0 (true for every call).
// ACT: 0 = none, 1 = elu, 2 = softplus+0.1
template <int ACT>
__global__ __launch_bounds__(256, 2) void gemm_bias_act(
    const float* __restrict__ A, long lda,
    const float* __restrict__ W,            // [N,K] row-major
    const float* __restrict__ bias,         // [N]
    float* __restrict__ C, long ldc,
    int K)
{
    __shared__ __align__(16) float As[16][64];
    __shared__ __align__(16) float Ws[16][64];

    const int tid  = threadIdx.x;
    const long m0  = (long)blockIdx.y * 64;
    const long n0  = (long)blockIdx.x * 64;

    // tile-load mapping: each thread loads one float4 of A and one of W
    const int lrow = tid >> 2;          // 0..63
    const int lkq  = (tid & 3) * 4;     // 0,4,8,12

    // compute mapping: 16 m-groups x 16 n-groups
    const int tmi = (tid & 15) * 4;     // m offset within tile
    const int tni = (tid >> 4) * 4;     // n offset within tile

    unsigned long long acc[4][2];
#pragma unroll
    for (int m = 0; m < 4; m++) { acc[m][0] = 0ull; acc[m][1] = 0ull; }

    const float* Aptr = A + (m0 + lrow) * lda + lkq;
    const float* Wptr = W + (n0 + lrow) * (long)K + lkq;

    for (int k0 = 0; k0 < K; k0 += 16) {
        float4 av = *(const float4*)(Aptr + k0);
        float4 wv = *(const float4*)(Wptr + k0);
        As[lkq + 0][lrow] = av.x;
        As[lkq + 1][lrow] = av.y;
        As[lkq + 2][lrow] = av.z;
        As[lkq + 3][lrow] = av.w;
        Ws[lkq + 0][lrow] = wv.x;
        Ws[lkq + 1][lrow] = wv.y;
        Ws[lkq + 2][lrow] = wv.z;
        Ws[lkq + 3][lrow] = wv.w;
        __syncthreads();

#pragma unroll
        for (int kk = 0; kk < 16; kk++) {
            float4 a = *(const float4*)&As[kk][tmi];
            double2 b = *(const double2*)&Ws[kk][tni];
            unsigned long long b0 = __double_as_longlong(b.x);
            unsigned long long b1 = __double_as_longlong(b.y);
            float am[4] = {a.x, a.y, a.z, a.w};
#pragma unroll
            for (int m = 0; m < 4; m++) {
                unsigned long long a2 = pack2(am[m], am[m]);
                fma2(acc[m][0], a2, b0);
                fma2(acc[m][1], a2, b1);
            }
        }
        __syncthreads();
    }

    // epilogue
    float4 bv = *(const float4*)&bias[n0 + tni];
#pragma unroll
    for (int m = 0; m < 4; m++) {
        float2 c01 = unpack2(acc[m][0]);
        float2 c23 = unpack2(acc[m][1]);
        float4 cv;
        cv.x = c01.x + bv.x;
        cv.y = c01.y + bv.y;
        cv.z = c23.x + bv.z;
        cv.w = c23.y + bv.w;
        if (ACT == 1) {
            cv.x = act_elu(cv.x); cv.y = act_elu(cv.y);
            cv.z = act_elu(cv.z); cv.w = act_elu(cv.w);
        } else if (ACT == 2) {
            cv.x = act_softplus01(cv.x); cv.y = act_softplus01(cv.y);
            cv.z = act_softplus01(cv.z); cv.w = act_softplus01(cv.w);
        }
        *(float4*)&C[(m0 + tmi + m) * ldc + n0 + tni] = cv;
    }
}

// ---------------- GRU gate fusion -------------------------------------------
// h_new = (1-z)*n + z*h ; writes the hidden output for this timestep.
__global__ __launch_bounds__(256) void gru_gates(
    const float* __restrict__ gx_t,   // [B, 3*CH]
    const float* __restrict__ gh,     // [B, 3*CH]
    const float* __restrict__ h_prev, // [B, CH]
    float* __restrict__ h_out)        // [B, CH]
{
    int idx = blockIdx.x * blockDim.x + threadIdx.x;   // 0 .. B*CH-1
    int b = idx >> 11;          // / 2048
    int j = idx & 2047;         // % 2048
    const float* gxr = gx_t + (size_t)b * G_;
    const float* ghr = gh   + (size_t)b * G_;
    float xr = gxr[j],          hr = ghr[j];
    float xz = gxr[CH_ + j],    hz = ghr[CH_ + j];
    float xn = gxr[2*CH_ + j],  hn = ghr[2*CH_ + j];
    float r = 1.0f / (1.0f + expf(-(xr + hr)));
    float z = 1.0f / (1.0f + expf(-(xz + hz)));
    float n = tanhf(xn + r * hn);
    float h = h_prev[idx];
    h_out[idx] = (1.0f - z) * n + z * h;
}

// ---------------- launch -----------------------------------------------------
extern "C" void kernel_launch(void* const* d_in, const int* in_sizes, int n_in,
                              void* d_out, int out_size)
{
    const float* x    = (const float*)d_in[0];
    const float* We   = (const float*)d_in[1];
    const float* be   = (const float*)d_in[2];
    const float* Wih  = (const float*)d_in[3];
    const float* bih  = (const float*)d_in[4];
    const float* Whh  = (const float*)d_in[5];
    const float* bhh  = (const float*)d_in[6];
    const float* Wmu  = (const float*)d_in[7];
    const float* bmu  = (const float*)d_in[8];
    const float* Wsig = (const float*)d_in[9];
    const float* bsig = (const float*)d_in[10];

    float* out        = (float*)d_out;
    float* out_mu     = out;
    float* out_sig    = out + (size_t)MB_ * DOUT_;
    float* out_hidden = out + (size_t)2 * MB_ * DOUT_;

    float *p_xe, *p_gx, *p_gh, *p_h0;
    cudaGetSymbolAddress((void**)&p_xe, g_xe);
    cudaGetSymbolAddress((void**)&p_gx, g_gx);
    cudaGetSymbolAddress((void**)&p_gh, g_gh);
    cudaGetSymbolAddress((void**)&p_h0, g_h0);

    dim3 blk(256);

    // 1) xe = elu(x @ We^T + be)           [16384,1024], K=512
    gemm_bias_act<1><<<dim3(H_/64, MB_/64), blk>>>(x, DIN_, We, be, p_xe, H_, DIN_);

    // 2) gx = xe @ Wih^T + bih             [16384,6144], K=1024
    gemm_bias_act<0><<<dim3(G_/64, MB_/64), blk>>>(p_xe, H_, Wih, bih, p_gx, G_, H_);

    // 3) recurrence: 256 sequential steps
    for (int t = 0; t < T_; t++) {
        const float* hp = (t == 0) ? p_h0
                                   : out_hidden + (size_t)(t - 1) * B_ * CH_;
        // gh = h_prev @ Whh^T + bhh        [64,6144], K=2048
        gemm_bias_act<0><<<dim3(G_/64, B_/64), blk>>>(hp, CH_, Whh, bhh, p_gh, G_, CH_);
        // gates + hidden[t]
        gru_gates<<<(B_ * CH_) / 256, 256>>>(
            p_gx + (size_t)t * B_ * G_, p_gh, hp,
            out_hidden + (size_t)t * B_ * CH_);
    }

    // 4) mu = elu(h_mu @ Wmu^T + bmu)      [16384,512], K=1024, A = hidden[:, :1024]
    gemm_bias_act<1><<<dim3(DOUT_/64, MB_/64), blk>>>(out_hidden, CH_, Wmu, bmu,
                                                      out_mu, DOUT_, H_);
    // 5) sig = softplus(h_sig @ Wsig^T + bsig) + 0.1, A = hidden[:, 1024:]
    gemm_bias_act<2><<<dim3(DOUT_/64, MB_/64), blk>>>(out_hidden + H_, CH_, Wsig, bsig,
                                                      out_sig, DOUT_, H_);
}

// round 2
// speedup vs baseline: 1.0128x; 1.0128x over previous
#include <cuda_runtime.h>
#include <cstdint>
#include <cstddef>

// Problem constants
#define T_    256
#define B_    64
#define DIN_  512
#define H_    1024
#define CH_   2048          // 2*H
#define G_    6144          // 3*CH
#define DOUT_ 512
#define MB_   (T_*B_)       // 16384
#define KSPLIT 3

// ---------------- scratch (device globals; no allocations allowed) ----------
__device__ float g_xe[(size_t)MB_ * H_];              // 64 MB
__device__ float g_gx[(size_t)MB_ * G_];              // 402 MB
__device__ float g_ghp[(size_t)KSPLIT * B_ * G_];     // 4.7 MB
__device__ float g_h0[(size_t)B_ * CH_];              // zeros (.bss)

typedef unsigned long long u64;

// ---------------- packed fp32x2 helpers (FFMA2) ------------------------------
__device__ __forceinline__ void fma2(u64& a, u64 x, u64 y) {
    asm("fma.rn.f32x2 %0, %1, %2, %0;" : "+l"(a) : "l"(x), "l"(y));
}
__device__ __forceinline__ float2 unpack2(u64 v) {
    float2 f;
    asm("mov.b64 {%0, %1}, %2;" : "=f"(f.x), "=f"(f.y) : "l"(v));
    return f;
}

// ---------------- activations ------------------------------------------------
__device__ __forceinline__ float act_elu(float v) {
    return v > 0.0f ? v : expm1f(v);
}
__device__ __forceinline__ float act_softplus01(float v) {
    return fmaxf(v, 0.0f) + log1pf(expf(-fabsf(v))) + 0.1f;
}

// =============================================================================
// GEMM v2: C[M,N] = act(A[M,K] @ W[N,K]^T + bias[N])
// BM=128, BN=128, BK=16, 256 threads, 8m x 8n micro-tile, FFMA2 everywhere.
// A pairs come straight from shared (m-contiguous); B is stored DUPLICATED in
// shared so b-pairs also come straight from shared. No pack MOVs in mainloop.
// Requires: M%128==0, N%128==0, K%16==0, K>=32.
// =============================================================================
template <int ACT>
__global__ __launch_bounds__(256) void gemm128(
    const float* __restrict__ A, int lda,
    const float* __restrict__ W, int ldw,     // [N,K] row-major
    const float* __restrict__ bias,
    float* __restrict__ C, int ldc,
    int K)
{
    __shared__ __align__(16) float As[2][16][128];   // [kk][m]
    __shared__ __align__(16) float Bs[2][16][256];   // [kk][2n..2n+1] duplicated

    const int tid = threadIdx.x;
    const long m0 = (long)blockIdx.y * 128;
    const long n0 = (long)blockIdx.x * 128;

    const int ni = tid & 15;        // n-group: 8 cols each
    const int mi = tid >> 4;        // m-group: 8 rows each

    // loaders: each thread loads 2 float4 of A and 2 float4 of W per k-tile
    const int lm = tid >> 1;            // 0..127 (row of A-tile / W-tile)
    const int lk = (tid & 1) * 8;       // 0 or 8

    const float* Ap = A + (m0 + lm) * (long)lda + lk;
    const float* Wp = W + (n0 + lm) * (long)ldw + lk;

    u64 acc[4][8];
#pragma unroll
    for (int i = 0; i < 4; i++)
#pragma unroll
        for (int j = 0; j < 8; j++) acc[i][j] = 0ull;

    const int ntiles = K >> 4;

    // prologue: load tile 0
    float4 ra0 = *(const float4*)(Ap);
    float4 ra1 = *(const float4*)(Ap + 4);
    float4 rb0 = *(const float4*)(Wp);
    float4 rb1 = *(const float4*)(Wp + 4);
    {
        As[0][lk+0][lm] = ra0.x; As[0][lk+1][lm] = ra0.y;
        As[0][lk+2][lm] = ra0.z; As[0][lk+3][lm] = ra0.w;
        As[0][lk+4][lm] = ra1.x; As[0][lk+5][lm] = ra1.y;
        As[0][lk+6][lm] = ra1.z; As[0][lk+7][lm] = ra1.w;
        *(float2*)&Bs[0][lk+0][2*lm] = make_float2(rb0.x, rb0.x);
        *(float2*)&Bs[0][lk+1][2*lm] = make_float2(rb0.y, rb0.y);
        *(float2*)&Bs[0][lk+2][2*lm] = make_float2(rb0.z, rb0.z);
        *(float2*)&Bs[0][lk+3][2*lm] = make_float2(rb0.w, rb0.w);
        *(float2*)&Bs[0][lk+4][2*lm] = make_float2(rb1.x, rb1.x);
        *(float2*)&Bs[0][lk+5][2*lm] = make_float2(rb1.y, rb1.y);
        *(float2*)&Bs[0][lk+6][2*lm] = make_float2(rb1.z, rb1.z);
        *(float2*)&Bs[0][lk+7][2*lm] = make_float2(rb1.w, rb1.w);
    }
    __syncthreads();

    int buf = 0;
    for (int kt = 0; kt < ntiles; kt++) {
        const bool more = (kt + 1 < ntiles);
        if (more) {
            const float* ap = Ap + (kt + 1) * 16;
            const float* wp = Wp + (kt + 1) * 16;
            ra0 = *(const float4*)(ap);
            ra1 = *(const float4*)(ap + 4);
            rb0 = *(const float4*)(wp);
            rb1 = *(const float4*)(wp + 4);
        }

#pragma unroll
        for (int kk = 0; kk < 16; kk++) {
            ulonglong2 a01 = *(const ulonglong2*)&As[buf][kk][mi*8];
            ulonglong2 a23 = *(const ulonglong2*)&As[buf][kk][mi*8 + 4];
            ulonglong2 b01 = *(const ulonglong2*)&Bs[buf][kk][ni*16];
            ulonglong2 b23 = *(const ulonglong2*)&Bs[buf][kk][ni*16 + 4];
            ulonglong2 b45 = *(const ulonglong2*)&Bs[buf][kk][ni*16 + 8];
            ulonglong2 b67 = *(const ulonglong2*)&Bs[buf][kk][ni*16 + 12];
            u64 ap4[4] = {a01.x, a01.y, a23.x, a23.y};
            u64 bp8[8] = {b01.x, b01.y, b23.x, b23.y,
                          b45.x, b45.y, b67.x, b67.y};
#pragma unroll
            for (int mp = 0; mp < 4; mp++)
#pragma unroll
                for (int n = 0; n < 8; n++)
                    fma2(acc[mp][n], ap4[mp], bp8[n]);
        }

        if (more) {
            const int nb = buf ^ 1;
            As[nb][lk+0][lm] = ra0.x; As[nb][lk+1][lm] = ra0.y;
            As[nb][lk+2][lm] = ra0.z; As[nb][lk+3][lm] = ra0.w;
            As[nb][lk+4][lm] = ra1.x; As[nb][lk+5][lm] = ra1.y;
            As[nb][lk+6][lm] = ra1.z; As[nb][lk+7][lm] = ra1.w;
            *(float2*)&Bs[nb][lk+0][2*lm] = make_float2(rb0.x, rb0.x);
            *(float2*)&Bs[nb][lk+1][2*lm] = make_float2(rb0.y, rb0.y);
            *(float2*)&Bs[nb][lk+2][2*lm] = make_float2(rb0.z, rb0.z);
            *(float2*)&Bs[nb][lk+3][2*lm] = make_float2(rb0.w, rb0.w);
            *(float2*)&Bs[nb][lk+4][2*lm] = make_float2(rb1.x, rb1.x);
            *(float2*)&Bs[nb][lk+5][2*lm] = make_float2(rb1.y, rb1.y);
            *(float2*)&Bs[nb][lk+6][2*lm] = make_float2(rb1.z, rb1.z);
            *(float2*)&Bs[nb][lk+7][2*lm] = make_float2(rb1.w, rb1.w);
            __syncthreads();
        }
        buf ^= 1;
    }

    // epilogue
    float4 bv0 = *(const float4*)&bias[n0 + ni*8];
    float4 bv1 = *(const float4*)&bias[n0 + ni*8 + 4];
    float bv[8] = {bv0.x, bv0.y, bv0.z, bv0.w, bv1.x, bv1.y, bv1.z, bv1.w};

#pragma unroll
    for (int mp = 0; mp < 4; mp++) {
#pragma unroll
        for (int p = 0; p < 2; p++) {
            const long row = m0 + mi*8 + 2*mp + p;
            float o[8];
#pragma unroll
            for (int n = 0; n < 8; n++) {
                float2 c = unpack2(acc[mp][n]);
                float v = (p ? c.y : c.x) + bv[n];
                if (ACT == 1) v = act_elu(v);
                else if (ACT == 2) v = act_softplus01(v);
                o[n] = v;
            }
            float* cp = &C[row * (long)ldc + n0 + ni*8];
            *(float4*)(cp)     = make_float4(o[0], o[1], o[2], o[3]);
            *(float4*)(cp + 4) = make_float4(o[4], o[5], o[6], o[7]);
        }
    }
}

// =============================================================================
// Recurrence GEMM: Cp[ks] = h_prev[64, kchunk] @ Whh[6144, kchunk]^T
// BM=64, BN=128, BK=16, 256 threads, 8m x 4n micro, split-K over 3 chunks.
// grid = (48, 3) = 144 CTAs = one full wave.
// =============================================================================
__global__ __launch_bounds__(256) void gemm_step(
    const float* __restrict__ A,   // [64, 2048]
    const float* __restrict__ W,   // [6144, 2048]
    float* __restrict__ Cp)        // [KSPLIT][64][6144]
{
    __shared__ __align__(16) float As[2][16][64];
    __shared__ __align__(16) float Bs[2][16][256];

    const int tid = threadIdx.x;
    const long n0 = (long)blockIdx.x * 128;
    const int ks  = blockIdx.y;
    const int kbeg   = ks * 688;                 // 688 = 43*16
    const int ntiles = (ks == 2) ? 42 : 43;      // 43,43,42 -> 2048 total

    const int ni = tid & 31;     // 4 cols each -> 128
    const int mi = tid >> 5;     // 8 rows each -> 64

    // A loader: 64x16 floats, 1 float4/thread
    const int alm = tid & 63;
    const int alk = (tid >> 6) * 4;     // 0,4,8,12
    // B loader: 128x16 floats, 2 float4/thread
    const int blm = tid >> 1;
    const int blk = (tid & 1) * 8;

    const float* Ap = A + alm * (long)CH_ + kbeg + alk;
    const float* Wp = W + (n0 + blm) * (long)CH_ + kbeg + blk;

    u64 acc[4][4];
#pragma unroll
    for (int i = 0; i < 4; i++)
#pragma unroll
        for (int j = 0; j < 4; j++) acc[i][j] = 0ull;

    float4 ra  = *(const float4*)(Ap);
    float4 rb0 = *(const float4*)(Wp);
    float4 rb1 = *(const float4*)(Wp + 4);
    {
        As[0][alk+0][alm] = ra.x; As[0][alk+1][alm] = ra.y;
        As[0][alk+2][alm] = ra.z; As[0][alk+3][alm] = ra.w;
        *(float2*)&Bs[0][blk+0][2*blm] = make_float2(rb0.x, rb0.x);
        *(float2*)&Bs[0][blk+1][2*blm] = make_float2(rb0.y, rb0.y);
        *(float2*)&Bs[0][blk+2][2*blm] = make_float2(rb0.z, rb0.z);
        *(float2*)&Bs[0][blk+3][2*blm] = make_float2(rb0.w, rb0.w);
        *(float2*)&Bs[0][blk+4][2*blm] = make_float2(rb1.x, rb1.x);
        *(float2*)&Bs[0][blk+5][2*blm] = make_float2(rb1.y, rb1.y);
        *(float2*)&Bs[0][blk+6][2*blm] = make_float2(rb1.z, rb1.z);
        *(float2*)&Bs[0][blk+7][2*blm] = make_float2(rb1.w, rb1.w);
    }
    __syncthreads();

    int buf = 0;
    for (int kt = 0; kt < ntiles; kt++) {
        const bool more = (kt + 1 < ntiles);
        if (more) {
            ra  = *(const float4*)(Ap + (kt + 1) * 16);
            rb0 = *(const float4*)(Wp + (kt + 1) * 16);
            rb1 = *(const float4*)(Wp + (kt + 1) * 16 + 4);
        }

#pragma unroll
        for (int kk = 0; kk < 16; kk++) {
            ulonglong2 a01 = *(const ulonglong2*)&As[buf][kk][mi*8];
            ulonglong2 a23 = *(const ulonglong2*)&As[buf][kk][mi*8 + 4];
            ulonglong2 b01 = *(const ulonglong2*)&Bs[buf][kk][ni*8];
            ulonglong2 b23 = *(const ulonglong2*)&Bs[buf][kk][ni*8 + 4];
            u64 ap4[4] = {a01.x, a01.y, a23.x, a23.y};
            u64 bp4[4] = {b01.x, b01.y, b23.x, b23.y};
#pragma unroll
            for (int mp = 0; mp < 4; mp++)
#pragma unroll
                for (int n = 0; n < 4; n++)
                    fma2(acc[mp][n], ap4[mp], bp4[n]);
        }

        if (more) {
            const int nb = buf ^ 1;
            As[nb][alk+0][alm] = ra.x; As[nb][alk+1][alm] = ra.y;
            As[nb][alk+2][alm] = ra.z; As[nb][alk+3][alm] = ra.w;
            *(float2*)&Bs[nb][blk+0][2*blm] = make_float2(rb0.x, rb0.x);
            *(float2*)&Bs[nb][blk+1][2*blm] = make_float2(rb0.y, rb0.y);
            *(float2*)&Bs[nb][blk+2][2*blm] = make_float2(rb0.z, rb0.z);
            *(float2*)&Bs[nb][blk+3][2*blm] = make_float2(rb0.w, rb0.w);
            *(float2*)&Bs[nb][blk+4][2*blm] = make_float2(rb1.x, rb1.x);
            *(float2*)&Bs[nb][blk+5][2*blm] = make_float2(rb1.y, rb1.y);
            *(float2*)&Bs[nb][blk+6][2*blm] = make_float2(rb1.z, rb1.z);
            *(float2*)&Bs[nb][blk+7][2*blm] = make_float2(rb1.w, rb1.w);
            __syncthreads();
        }
        buf ^= 1;
    }

    // epilogue: write partials (no bias; added in gates kernel)
    float* base = Cp + (size_t)ks * B_ * G_;
#pragma unroll
    for (int mp = 0; mp < 4; mp++) {
#pragma unroll
        for (int p = 0; p < 2; p++) {
            const int row = mi*8 + 2*mp + p;
            float o[4];
#pragma unroll
            for (int n = 0; n < 4; n++) {
                float2 c = unpack2(acc[mp][n]);
                o[n] = p ? c.y : c.x;
            }
            *(float4*)&base[row * (long)G_ + n0 + ni*4] =
                make_float4(o[0], o[1], o[2], o[3]);
        }
    }
}

// =============================================================================
// GRU gate fusion: reduce KSPLIT partials + bhh, compute h_new. float4 lanes.
// =============================================================================
__global__ __launch_bounds__(256) void gru_gates(
    const float* __restrict__ gx_t,   // [B, 3*CH]
    const float* __restrict__ ghp,    // [KSPLIT, B, 3*CH]
    const float* __restrict__ bhh,    // [3*CH]
    const float* __restrict__ h_prev, // [B, CH]
    float* __restrict__ h_out)        // [B, CH]
{
    const int idx4 = blockIdx.x * blockDim.x + threadIdx.x; // 0..B*CH/4-1
    const int b  = idx4 >> 9;          // CH/4 = 512
    const int j4 = idx4 & 511;
    const long go = (long)b * G_ + j4 * 4;

    float4 xr = *(const float4*)(gx_t + go);
    float4 xz = *(const float4*)(gx_t + go + CH_);
    float4 xn = *(const float4*)(gx_t + go + 2*CH_);

    float4 hr = *(const float4*)(ghp + go);
    float4 hz = *(const float4*)(ghp + go + CH_);
    float4 hn = *(const float4*)(ghp + go + 2*CH_);
#pragma unroll
    for (int s = 1; s < KSPLIT; s++) {
        const float* p = ghp + (size_t)s * B_ * G_ + go;
        float4 a = *(const float4*)(p);
        float4 c = *(const float4*)(p + CH_);
        float4 d = *(const float4*)(p + 2*CH_);
        hr.x += a.x; hr.y += a.y; hr.z += a.z; hr.w += a.w;
        hz.x += c.x; hz.y += c.y; hz.z += c.z; hz.w += c.w;
        hn.x += d.x; hn.y += d.y; hn.z += d.z; hn.w += d.w;
    }
    float4 br = *(const float4*)(bhh + j4*4);
    float4 bz = *(const float4*)(bhh + CH_ + j4*4);
    float4 bn = *(const float4*)(bhh + 2*CH_ + j4*4);
    float4 hp = *(const float4*)(h_prev + (long)b * CH_ + j4*4);

    float4 out;
    {
        float xrv[4] = {xr.x, xr.y, xr.z, xr.w};
        float xzv[4] = {xz.x, xz.y, xz.z, xz.w};
        float xnv[4] = {xn.x, xn.y, xn.z, xn.w};
        float hrv[4] = {hr.x + br.x, hr.y + br.y, hr.z + br.z, hr.w + br.w};
        float hzv[4] = {hz.x + bz.x, hz.y + bz.y, hz.z + bz.z, hz.w + bz.w};
        float hnv[4] = {hn.x + bn.x, hn.y + bn.y, hn.z + bn.z, hn.w + bn.w};
        float hpv[4] = {hp.x, hp.y, hp.z, hp.w};
        float ov[4];
#pragma unroll
        for (int i = 0; i < 4; i++) {
            float r = 1.0f / (1.0f + expf(-(xrv[i] + hrv[i])));
            float z = 1.0f / (1.0f + expf(-(xzv[i] + hzv[i])));
            float n = tanhf(xnv[i] + r * hnv[i]);
            ov[i] = (1.0f - z) * n + z * hpv[i];
        }
        out = make_float4(ov[0], ov[1], ov[2], ov[3]);
    }
    *(float4*)(h_out + (long)b * CH_ + j4*4) = out;
}

// =============================================================================
// launch
// =============================================================================
extern "C" void kernel_launch(void* const* d_in, const int* in_sizes, int n_in,
                              void* d_out, int out_size)
{
    const float* x    = (const float*)d_in[0];
    const float* We   = (const float*)d_in[1];
    const float* be   = (const float*)d_in[2];
    const float* Wih  = (const float*)d_in[3];
    const float* bih  = (const float*)d_in[4];
    const float* Whh  = (const float*)d_in[5];
    const float* bhh  = (const float*)d_in[6];
    const float* Wmu  = (const float*)d_in[7];
    const float* bmu  = (const float*)d_in[8];
    const float* Wsig = (const float*)d_in[9];
    const float* bsig = (const float*)d_in[10];

    float* out        = (float*)d_out;
    float* out_mu     = out;
    float* out_sig    = out + (size_t)MB_ * DOUT_;
    float* out_hidden = out + (size_t)2 * MB_ * DOUT_;

    float *p_xe, *p_gx, *p_ghp, *p_h0;
    cudaGetSymbolAddress((void**)&p_xe, g_xe);
    cudaGetSymbolAddress((void**)&p_gx, g_gx);
    cudaGetSymbolAddress((void**)&p_ghp, g_ghp);
    cudaGetSymbolAddress((void**)&p_h0, g_h0);

    dim3 blk(256);

    // 1) xe = elu(x @ We^T + be)        [16384,1024], K=512
    gemm128<1><<<dim3(H_/128, MB_/128), blk>>>(x, DIN_, We, DIN_, be,
                                               p_xe, H_, DIN_);
    // 2) gx = xe @ Wih^T + bih          [16384,6144], K=1024
    gemm128<0><<<dim3(G_/128, MB_/128), blk>>>(p_xe, H_, Wih, H_, bih,
                                               p_gx, G_, H_);
    // 3) recurrence
    for (int t = 0; t < T_; t++) {
        const float* hp = (t == 0) ? p_h0
                                   : out_hidden + (size_t)(t - 1) * B_ * CH_;
        gemm_step<<<dim3(G_/128, KSPLIT), blk>>>(hp, Whh, p_ghp);
        gru_gates<<<(B_ * CH_ / 4) / 256, blk>>>(
            p_gx + (size_t)t * B_ * G_, p_ghp, bhh, hp,
            out_hidden + (size_t)t * B_ * CH_);
    }
    // 4) mu = elu(h_mu @ Wmu^T + bmu)   [16384,512], K=1024
    gemm128<1><<<dim3(DOUT_/128, MB_/128), blk>>>(out_hidden, CH_, Wmu, H_, bmu,
                                                  out_mu, DOUT_, H_);
    // 5) sig = softplus(...) + 0.1
    gemm128<2><<<dim3(DOUT_/128, MB_/128), blk>>>(out_hidden + H_, CH_, Wsig, H_, bsig,
                                                  out_sig, DOUT_, H_);
}

// round 3
// speedup vs baseline: 1.5992x; 1.5790x over previous
#include <cuda_runtime.h>
#include <cstdint>
#include <cstddef>

// Problem constants
#define T_    256
#define B_    64
#define DIN_  512
#define H_    1024
#define CH_   2048          // 2*H
#define G_    6144          // 3*CH
#define DOUT_ 512
#define MB_   (T_*B_)       // 16384
#define KSPLIT 3
#define NCTA_STEP (48 * KSPLIT)   // 144 CTAs — all resident (148 SMs)

// ---------------- scratch (device globals) ----------------------------------
__device__ float g_xe[(size_t)MB_ * H_];
__device__ float g_gx[(size_t)MB_ * G_];
__device__ float g_ghp[(size_t)KSPLIT * B_ * G_];
__device__ float g_h0[(size_t)B_ * CH_];
__device__ unsigned int g_cnt[T_];

typedef unsigned long long u64;

__device__ __forceinline__ void fma2(u64& a, u64 x, u64 y) {
    asm("fma.rn.f32x2 %0, %1, %2, %0;" : "+l"(a) : "l"(x), "l"(y));
}
__device__ __forceinline__ float2 unpack2(u64 v) {
    float2 f;
    asm("mov.b64 {%0, %1}, %2;" : "=f"(f.x), "=f"(f.y) : "l"(v));
    return f;
}

__device__ __forceinline__ float act_elu(float v) {
    return v > 0.0f ? v : expm1f(v);
}
__device__ __forceinline__ float act_softplus01(float v) {
    return fmaxf(v, 0.0f) + log1pf(expf(-fabsf(v))) + 0.1f;
}

// =============================================================================
// init: zero h0 and the per-step arrival counters (must be re-zeroed each run)
// Also shifts launch parity so ncu -s 5 profiles a step kernel.
// =============================================================================
__global__ void init_kernel() {
    int idx = blockIdx.x * 256 + threadIdx.x;
    if (idx < B_ * CH_) g_h0[idx] = 0.0f;
    if (idx < T_) g_cnt[idx] = 0u;
}

// =============================================================================
// gemm_big: C[M,N] = act(A[M,K] @ W[N,K]^T + bias)
// BM=64, BN=256, BK=16, 256 threads (8 warps).
// Warp-uniform A: warp w owns rows w*8..w*8+7; lane l owns cols l*8..l*8+7.
// A stored duplicated in smem -> broadcast LDS (free); B stored plain.
// Per kk/thread: 32 FFMA2, 4 broadcast LDS.128 (A), 2 LDS.128 (B) -> FFMA2-bound.
// =============================================================================
template <int ACT>
__global__ __launch_bounds__(256) void gemm_big(
    const float* __restrict__ A, int lda,
    const float* __restrict__ W, int ldw,     // [N,K] row-major
    const float* __restrict__ bias,
    float* __restrict__ C, int ldc,
    int K)
{
    __shared__ __align__(16) float As[2][16][128];   // (a,a) pairs, 64 m-rows
    __shared__ __align__(16) float Bs[2][16][256];   // plain

    const int tid = threadIdx.x;
    const int w   = tid >> 5;
    const int l   = tid & 31;
    const long m0 = (long)blockIdx.y * 64;
    const long n0 = (long)blockIdx.x * 256;

    // loaders
    const int arow = tid & 63;
    const int ak   = (tid >> 6) * 4;          // 0,4,8,12
    const int brow = tid >> 1;                 // 0..127
    const int bk   = (tid & 1) * 8;            // 0,8

    const float* Ap  = A + (m0 + arow) * (long)lda + ak;
    const float* Wp0 = W + (n0 + brow) * (long)ldw + bk;
    const float* Wp1 = W + (n0 + brow + 128) * (long)ldw + bk;

    u64 acc[8][4];
#pragma unroll
    for (int i = 0; i < 8; i++)
#pragma unroll
        for (int j = 0; j < 4; j++) acc[i][j] = 0ull;

    const int ntiles = K >> 4;

    float4 ra  = *(const float4*)Ap;
    float4 rb0 = *(const float4*)(Wp0);
    float4 rb1 = *(const float4*)(Wp0 + 4);
    float4 rb2 = *(const float4*)(Wp1);
    float4 rb3 = *(const float4*)(Wp1 + 4);
    {
        *(float2*)&As[0][ak+0][2*arow] = make_float2(ra.x, ra.x);
        *(float2*)&As[0][ak+1][2*arow] = make_float2(ra.y, ra.y);
        *(float2*)&As[0][ak+2][2*arow] = make_float2(ra.z, ra.z);
        *(float2*)&As[0][ak+3][2*arow] = make_float2(ra.w, ra.w);
        Bs[0][bk+0][brow] = rb0.x; Bs[0][bk+1][brow] = rb0.y;
        Bs[0][bk+2][brow] = rb0.z; Bs[0][bk+3][brow] = rb0.w;
        Bs[0][bk+4][brow] = rb1.x; Bs[0][bk+5][brow] = rb1.y;
        Bs[0][bk+6][brow] = rb1.z; Bs[0][bk+7][brow] = rb1.w;
        Bs[0][bk+0][brow+128] = rb2.x; Bs[0][bk+1][brow+128] = rb2.y;
        Bs[0][bk+2][brow+128] = rb2.z; Bs[0][bk+3][brow+128] = rb2.w;
        Bs[0][bk+4][brow+128] = rb3.x; Bs[0][bk+5][brow+128] = rb3.y;
        Bs[0][bk+6][brow+128] = rb3.z; Bs[0][bk+7][brow+128] = rb3.w;
    }
    __syncthreads();

    int buf = 0;
    for (int kt = 0; kt < ntiles; kt++) {
        const bool more = (kt + 1 < ntiles);
        if (more) {
            const int o = (kt + 1) * 16;
            ra  = *(const float4*)(Ap + o);
            rb0 = *(const float4*)(Wp0 + o);
            rb1 = *(const float4*)(Wp0 + o + 4);
            rb2 = *(const float4*)(Wp1 + o);
            rb3 = *(const float4*)(Wp1 + o + 4);
        }

#pragma unroll
        for (int kk = 0; kk < 16; kk++) {
            // A fragment: 8 (a,a) pairs, warp-uniform address -> broadcast
            ulonglong2 a01 = *(const ulonglong2*)&As[buf][kk][16*w];
            ulonglong2 a23 = *(const ulonglong2*)&As[buf][kk][16*w + 4];
            ulonglong2 a45 = *(const ulonglong2*)&As[buf][kk][16*w + 8];
            ulonglong2 a67 = *(const ulonglong2*)&As[buf][kk][16*w + 12];
            // B fragment: 4 natural (b[n],b[n+1]) pairs
            ulonglong2 b01 = *(const ulonglong2*)&Bs[buf][kk][l*8];
            ulonglong2 b23 = *(const ulonglong2*)&Bs[buf][kk][l*8 + 4];
            u64 av[8] = {a01.x, a01.y, a23.x, a23.y, a45.x, a45.y, a67.x, a67.y};
            u64 bv[4] = {b01.x, b01.y, b23.x, b23.y};
#pragma unroll
            for (int m = 0; m < 8; m++)
#pragma unroll
                for (int j = 0; j < 4; j++)
                    fma2(acc[m][j], av[m], bv[j]);
        }

        if (more) {
            const int nb = buf ^ 1;
            *(float2*)&As[nb][ak+0][2*arow] = make_float2(ra.x, ra.x);
            *(float2*)&As[nb][ak+1][2*arow] = make_float2(ra.y, ra.y);
            *(float2*)&As[nb][ak+2][2*arow] = make_float2(ra.z, ra.z);
            *(float2*)&As[nb][ak+3][2*arow] = make_float2(ra.w, ra.w);
            Bs[nb][bk+0][brow] = rb0.x; Bs[nb][bk+1][brow] = rb0.y;
            Bs[nb][bk+2][brow] = rb0.z; Bs[nb][bk+3][brow] = rb0.w;
            Bs[nb][bk+4][brow] = rb1.x; Bs[nb][bk+5][brow] = rb1.y;
            Bs[nb][bk+6][brow] = rb1.z; Bs[nb][bk+7][brow] = rb1.w;
            Bs[nb][bk+0][brow+128] = rb2.x; Bs[nb][bk+1][brow+128] = rb2.y;
            Bs[nb][bk+2][brow+128] = rb2.z; Bs[nb][bk+3][brow+128] = rb2.w;
            Bs[nb][bk+4][brow+128] = rb3.x; Bs[nb][bk+5][brow+128] = rb3.y;
            Bs[nb][bk+6][brow+128] = rb3.z; Bs[nb][bk+7][brow+128] = rb3.w;
            __syncthreads();
        }
        buf ^= 1;
    }

    // epilogue
    float4 bv0 = *(const float4*)&bias[n0 + l*8];
    float4 bv1 = *(const float4*)&bias[n0 + l*8 + 4];
    float bb[8] = {bv0.x, bv0.y, bv0.z, bv0.w, bv1.x, bv1.y, bv1.z, bv1.w};

#pragma unroll
    for (int m = 0; m < 8; m++) {
        float o[8];
#pragma unroll
        for (int j = 0; j < 4; j++) {
            float2 c = unpack2(acc[m][j]);
            o[2*j]   = c.x + bb[2*j];
            o[2*j+1] = c.y + bb[2*j+1];
        }
#pragma unroll
        for (int j = 0; j < 8; j++) {
            if (ACT == 1) o[j] = act_elu(o[j]);
            else if (ACT == 2) o[j] = act_softplus01(o[j]);
        }
        float* cp = &C[(m0 + w*8 + m) * (long)ldc + n0 + l*8];
        *(float4*)(cp)     = make_float4(o[0], o[1], o[2], o[3]);
        *(float4*)(cp + 4) = make_float4(o[4], o[5], o[6], o[7]);
    }
}

// =============================================================================
// step_fused: one GRU timestep.
//   Phase 1 (144 CTAs, split-K=3): ghp[ks] = h_prev @ Whh[:, kchunk]^T
//   device-wide arrival counter (all CTAs resident -> deadlock-free)
//   Phase 2: reduce partials + bhh, gates, write hidden[t].
// BM=64 (all of M), BN=128; warp w -> rows w*8..w*8+7, lane l -> cols l*4..l*4+3.
// =============================================================================
__global__ __launch_bounds__(256) void step_fused(
    const float* __restrict__ h_prev,   // [64, 2048]
    const float* __restrict__ W,        // [6144, 2048]
    const float* __restrict__ gx_t,     // [64, 6144]
    const float* __restrict__ bhh,      // [6144]
    float* __restrict__ ghp,            // [KSPLIT][64][6144]
    float* __restrict__ h_out,          // [64, 2048]
    unsigned int* __restrict__ counter)
{
    __shared__ __align__(16) float As[2][16][128];   // (a,a) pairs, 64 rows
    __shared__ __align__(16) float Bs[2][16][128];   // plain

    const int tid = threadIdx.x;
    const int w   = tid >> 5;
    const int l   = tid & 31;
    const long n0 = (long)blockIdx.x * 128;
    const int ks  = blockIdx.y;
    const int kbeg   = ks * 688;                 // 43*16
    const int ntiles = (ks == 2) ? 42 : 43;

    // loaders
    const int arow = tid & 63;
    const int ak   = (tid >> 6) * 4;
    const int brow = tid >> 1;
    const int bk   = (tid & 1) * 8;

    const float* Ap = h_prev + arow * (long)CH_ + kbeg + ak;
    const float* Wp = W + (n0 + brow) * (long)CH_ + kbeg + bk;

    u64 acc[8][2];
#pragma unroll
    for (int i = 0; i < 8; i++) { acc[i][0] = 0ull; acc[i][1] = 0ull; }

    float4 ra  = *(const float4*)Ap;
    float4 rb0 = *(const float4*)(Wp);
    float4 rb1 = *(const float4*)(Wp + 4);
    {
        *(float2*)&As[0][ak+0][2*arow] = make_float2(ra.x, ra.x);
        *(float2*)&As[0][ak+1][2*arow] = make_float2(ra.y, ra.y);
        *(float2*)&As[0][ak+2][2*arow] = make_float2(ra.z, ra.z);
        *(float2*)&As[0][ak+3][2*arow] = make_float2(ra.w, ra.w);
        Bs[0][bk+0][brow] = rb0.x; Bs[0][bk+1][brow] = rb0.y;
        Bs[0][bk+2][brow] = rb0.z; Bs[0][bk+3][brow] = rb0.w;
        Bs[0][bk+4][brow] = rb1.x; Bs[0][bk+5][brow] = rb1.y;
        Bs[0][bk+6][brow] = rb1.z; Bs[0][bk+7][brow] = rb1.w;
    }
    __syncthreads();

    int buf = 0;
    for (int kt = 0; kt < ntiles; kt++) {
        const bool more = (kt + 1 < ntiles);
        if (more) {
            const int o = (kt + 1) * 16;
            ra  = *(const float4*)(Ap + o);
            rb0 = *(const float4*)(Wp + o);
            rb1 = *(const float4*)(Wp + o + 4);
        }

#pragma unroll
        for (int kk = 0; kk < 16; kk++) {
            ulonglong2 a01 = *(const ulonglong2*)&As[buf][kk][16*w];
            ulonglong2 a23 = *(const ulonglong2*)&As[buf][kk][16*w + 4];
            ulonglong2 a45 = *(const ulonglong2*)&As[buf][kk][16*w + 8];
            ulonglong2 a67 = *(const ulonglong2*)&As[buf][kk][16*w + 12];
            ulonglong2 b01 = *(const ulonglong2*)&Bs[buf][kk][l*4];
            u64 av[8] = {a01.x, a01.y, a23.x, a23.y, a45.x, a45.y, a67.x, a67.y};
#pragma unroll
            for (int m = 0; m < 8; m++) {
                fma2(acc[m][0], av[m], b01.x);
                fma2(acc[m][1], av[m], b01.y);
            }
        }

        if (more) {
            const int nb = buf ^ 1;
            *(float2*)&As[nb][ak+0][2*arow] = make_float2(ra.x, ra.x);
            *(float2*)&As[nb][ak+1][2*arow] = make_float2(ra.y, ra.y);
            *(float2*)&As[nb][ak+2][2*arow] = make_float2(ra.z, ra.z);
            *(float2*)&As[nb][ak+3][2*arow] = make_float2(ra.w, ra.w);
            Bs[nb][bk+0][brow] = rb0.x; Bs[nb][bk+1][brow] = rb0.y;
            Bs[nb][bk+2][brow] = rb0.z; Bs[nb][bk+3][brow] = rb0.w;
            Bs[nb][bk+4][brow] = rb1.x; Bs[nb][bk+5][brow] = rb1.y;
            Bs[nb][bk+6][brow] = rb1.z; Bs[nb][bk+7][brow] = rb1.w;
            __syncthreads();
        }
        buf ^= 1;
    }

    // write partials
    {
        float* base = ghp + (size_t)ks * B_ * G_;
#pragma unroll
        for (int m = 0; m < 8; m++) {
            float2 c0 = unpack2(acc[m][0]);
            float2 c1 = unpack2(acc[m][1]);
            *(float4*)&base[(w*8 + m) * (long)G_ + n0 + l*4] =
                make_float4(c0.x, c0.y, c1.x, c1.y);
        }
    }

    // ---- device-wide arrival barrier (144 CTAs, all resident) ----
    __threadfence();
    __syncthreads();
    if (tid == 0) {
        atomicAdd(counter, 1u);
        while (atomicAdd(counter, 0u) < (unsigned)NCTA_STEP) { }
    }
    __syncthreads();

    // ---- phase 2: gates. CTAs 0..127 each handle 256 float4 items ----
    const int cta = blockIdx.y * 48 + blockIdx.x;
    const int idx4 = cta * 256 + tid;
    if (idx4 < B_ * CH_ / 4) {
        const int b  = idx4 >> 9;            // CH/4 = 512
        const int j4 = idx4 & 511;
        const long go = (long)b * G_ + j4 * 4;

        float4 xr = *(const float4*)(gx_t + go);
        float4 xz = *(const float4*)(gx_t + go + CH_);
        float4 xn = *(const float4*)(gx_t + go + 2*CH_);

        float4 hr = *(const float4*)(ghp + go);
        float4 hz = *(const float4*)(ghp + go + CH_);
        float4 hn = *(const float4*)(ghp + go + 2*CH_);
#pragma unroll
        for (int s = 1; s < KSPLIT; s++) {
            const float* p = ghp + (size_t)s * B_ * G_ + go;
            float4 a = *(const float4*)(p);
            float4 c = *(const float4*)(p + CH_);
            float4 d = *(const float4*)(p + 2*CH_);
            hr.x += a.x; hr.y += a.y; hr.z += a.z; hr.w += a.w;
            hz.x += c.x; hz.y += c.y; hz.z += c.z; hz.w += c.w;
            hn.x += d.x; hn.y += d.y; hn.z += d.z; hn.w += d.w;
        }
        float4 br = *(const float4*)(bhh + j4*4);
        float4 bz = *(const float4*)(bhh + CH_ + j4*4);
        float4 bn = *(const float4*)(bhh + 2*CH_ + j4*4);
        float4 hp = *(const float4*)(h_prev + (long)b * CH_ + j4*4);

        float xrv[4] = {xr.x, xr.y, xr.z, xr.w};
        float xzv[4] = {xz.x, xz.y, xz.z, xz.w};
        float xnv[4] = {xn.x, xn.y, xn.z, xn.w};
        float hrv[4] = {hr.x + br.x, hr.y + br.y, hr.z + br.z, hr.w + br.w};
        float hzv[4] = {hz.x + bz.x, hz.y + bz.y, hz.z + bz.z, hz.w + bz.w};
        float hnv[4] = {hn.x + bn.x, hn.y + bn.y, hn.z + bn.z, hn.w + bn.w};
        float hpv[4] = {hp.x, hp.y, hp.z, hp.w};
        float ov[4];
#pragma unroll
        for (int i = 0; i < 4; i++) {
            float r = 1.0f / (1.0f + expf(-(xrv[i] + hrv[i])));
            float z = 1.0f / (1.0f + expf(-(xzv[i] + hzv[i])));
            float n = tanhf(xnv[i] + r * hnv[i]);
            ov[i] = (1.0f - z) * n + z * hpv[i];
        }
        *(float4*)(h_out + (long)b * CH_ + j4*4) =
            make_float4(ov[0], ov[1], ov[2], ov[3]);
    }
}

// =============================================================================
// launch
// =============================================================================
extern "C" void kernel_launch(void* const* d_in, const int* in_sizes, int n_in,
                              void* d_out, int out_size)
{
    const float* x    = (const float*)d_in[0];
    const float* We   = (const float*)d_in[1];
    const float* be   = (const float*)d_in[2];
    const float* Wih  = (const float*)d_in[3];
    const float* bih  = (const float*)d_in[4];
    const float* Whh  = (const float*)d_in[5];
    const float* bhh  = (const float*)d_in[6];
    const float* Wmu  = (const float*)d_in[7];
    const float* bmu  = (const float*)d_in[8];
    const float* Wsig = (const float*)d_in[9];
    const float* bsig = (const float*)d_in[10];

    float* out        = (float*)d_out;
    float* out_mu     = out;
    float* out_sig    = out + (size_t)MB_ * DOUT_;
    float* out_hidden = out + (size_t)2 * MB_ * DOUT_;

    float *p_xe, *p_gx, *p_ghp, *p_h0;
    unsigned int* p_cnt;
    cudaGetSymbolAddress((void**)&p_xe, g_xe);
    cudaGetSymbolAddress((void**)&p_gx, g_gx);
    cudaGetSymbolAddress((void**)&p_ghp, g_ghp);
    cudaGetSymbolAddress((void**)&p_h0, g_h0);
    cudaGetSymbolAddress((void**)&p_cnt, g_cnt);

    dim3 blk(256);

    // 0) zero h0 + barrier counters (also shifts ncu parity onto step_fused)
    init_kernel<<<(B_ * CH_) / 256, blk>>>();

    // 1) xe = elu(x @ We^T + be)        [16384,1024], K=512
    gemm_big<1><<<dim3(H_/256, MB_/64), blk>>>(x, DIN_, We, DIN_, be,
                                               p_xe, H_, DIN_);
    // 2) gx = xe @ Wih^T + bih          [16384,6144], K=1024
    gemm_big<0><<<dim3(G_/256, MB_/64), blk>>>(p_xe, H_, Wih, H_, bih,
                                               p_gx, G_, H_);
    // 3) recurrence: one fused kernel per step
    for (int t = 0; t < T_; t++) {
        const float* hp = (t == 0) ? p_h0
                                   : out_hidden + (size_t)(t - 1) * B_ * CH_;
        step_fused<<<dim3(48, KSPLIT), blk>>>(
            hp, Whh, p_gx + (size_t)t * B_ * G_, bhh, p_ghp,
            out_hidden + (size_t)t * B_ * CH_, p_cnt + t);
    }
    // 4) mu = elu(h_mu @ Wmu^T + bmu)   [16384,512], K=1024
    gemm_big<1><<<dim3(DOUT_/256, MB_/64), blk>>>(out_hidden, CH_, Wmu, H_, bmu,
                                                  out_mu, DOUT_, H_);
    // 5) sig = softplus(...) + 0.1
    gemm_big<2><<<dim3(DOUT_/256, MB_/64), blk>>>(out_hidden + H_, CH_, Wsig, H_, bsig,
                                                  out_sig, DOUT_, H_);
}

// round 4
// speedup vs baseline: 1.5999x; 1.0004x over previous
#include <cuda_runtime.h>
#include <cstdint>
#include <cstddef>

// Problem constants
#define T_    256
#define B_    64
#define DIN_  512
#define H_    1024
#define CH_   2048          // 2*H
#define G_    6144          // 3*CH
#define DOUT_ 512
#define MB_   (T_*B_)       // 16384
#define KSPLIT 3
#define NCTA_STEP (48 * KSPLIT)   // 144 CTAs — all resident (148 SMs)

// ---------------- scratch (device globals) ----------------------------------
__device__ float g_xe[(size_t)MB_ * H_];
__device__ float g_gx[(size_t)MB_ * G_];
__device__ float g_ghp[(size_t)KSPLIT * B_ * G_];
__device__ float g_h0[(size_t)B_ * CH_];
__device__ unsigned int g_cnt[T_];

typedef unsigned long long u64;

__device__ __forceinline__ void fma2(u64& a, u64 x, u64 y) {
    asm("fma.rn.f32x2 %0, %1, %2, %0;" : "+l"(a) : "l"(x), "l"(y));
}
__device__ __forceinline__ float2 unpack2(u64 v) {
    float2 f;
    asm("mov.b64 {%0, %1}, %2;" : "=f"(f.x), "=f"(f.y) : "l"(v));
    return f;
}

__device__ __forceinline__ float act_elu(float v) {
    return v > 0.0f ? v : expm1f(v);
}
__device__ __forceinline__ float act_softplus01(float v) {
    return fmaxf(v, 0.0f) + log1pf(expf(-fabsf(v))) + 0.1f;
}

// =============================================================================
// init: zero h0 and the per-step arrival counters (must be re-zeroed each run)
// Also shifts launch parity so ncu -s 5 profiles a step kernel.
// =============================================================================
__global__ void init_kernel() {
    int idx = blockIdx.x * 256 + threadIdx.x;
    if (idx < B_ * CH_) g_h0[idx] = 0.0f;
    if (idx < T_) g_cnt[idx] = 0u;
}

// =============================================================================
// gemm_big: C[M,N] = act(A[M,K] @ W[N,K]^T + bias)
// BM=64, BN=256, BK=16, 256 threads (8 warps).
// Warp-uniform A: warp w owns rows w*8..w*8+7; lane l owns cols l*8..l*8+7.
// A stored duplicated in smem -> broadcast LDS (free); B stored plain.
// Per kk/thread: 32 FFMA2, 4 broadcast LDS.128 (A), 2 LDS.128 (B) -> FFMA2-bound.
// =============================================================================
template <int ACT>
__global__ __launch_bounds__(256) void gemm_big(
    const float* __restrict__ A, int lda,
    const float* __restrict__ W, int ldw,     // [N,K] row-major
    const float* __restrict__ bias,
    float* __restrict__ C, int ldc,
    int K)
{
    __shared__ __align__(16) float As[2][16][128];   // (a,a) pairs, 64 m-rows
    __shared__ __align__(16) float Bs[2][16][256];   // plain

    const int tid = threadIdx.x;
    const int w   = tid >> 5;
    const int l   = tid & 31;
    const long m0 = (long)blockIdx.y * 64;
    const long n0 = (long)blockIdx.x * 256;

    // loaders
    const int arow = tid & 63;
    const int ak   = (tid >> 6) * 4;          // 0,4,8,12
    const int brow = tid >> 1;                 // 0..127
    const int bk   = (tid & 1) * 8;            // 0,8

    const float* Ap  = A + (m0 + arow) * (long)lda + ak;
    const float* Wp0 = W + (n0 + brow) * (long)ldw + bk;
    const float* Wp1 = W + (n0 + brow + 128) * (long)ldw + bk;

    u64 acc[8][4];
#pragma unroll
    for (int i = 0; i < 8; i++)
#pragma unroll
        for (int j = 0; j < 4; j++) acc[i][j] = 0ull;

    const int ntiles = K >> 4;

    float4 ra  = *(const float4*)Ap;
    float4 rb0 = *(const float4*)(Wp0);
    float4 rb1 = *(const float4*)(Wp0 + 4);
    float4 rb2 = *(const float4*)(Wp1);
    float4 rb3 = *(const float4*)(Wp1 + 4);
    {
        *(float2*)&As[0][ak+0][2*arow] = make_float2(ra.x, ra.x);
        *(float2*)&As[0][ak+1][2*arow] = make_float2(ra.y, ra.y);
        *(float2*)&As[0][ak+2][2*arow] = make_float2(ra.z, ra.z);
        *(float2*)&As[0][ak+3][2*arow] = make_float2(ra.w, ra.w);
        Bs[0][bk+0][brow] = rb0.x; Bs[0][bk+1][brow] = rb0.y;
        Bs[0][bk+2][brow] = rb0.z; Bs[0][bk+3][brow] = rb0.w;
        Bs[0][bk+4][brow] = rb1.x; Bs[0][bk+5][brow] = rb1.y;
        Bs[0][bk+6][brow] = rb1.z; Bs[0][bk+7][brow] = rb1.w;
        Bs[0][bk+0][brow+128] = rb2.x; Bs[0][bk+1][brow+128] = rb2.y;
        Bs[0][bk+2][brow+128] = rb2.z; Bs[0][bk+3][brow+128] = rb2.w;
        Bs[0][bk+4][brow+128] = rb3.x; Bs[0][bk+5][brow+128] = rb3.y;
        Bs[0][bk+6][brow+128] = rb3.z; Bs[0][bk+7][brow+128] = rb3.w;
    }
    __syncthreads();

    int buf = 0;
    for (int kt = 0; kt < ntiles; kt++) {
        const bool more = (kt + 1 < ntiles);
        if (more) {
            const int o = (kt + 1) * 16;
            ra  = *(const float4*)(Ap + o);
            rb0 = *(const float4*)(Wp0 + o);
            rb1 = *(const float4*)(Wp0 + o + 4);
            rb2 = *(const float4*)(Wp1 + o);
            rb3 = *(const float4*)(Wp1 + o + 4);
        }

#pragma unroll
        for (int kk = 0; kk < 16; kk++) {
            // A fragment: 8 (a,a) pairs, warp-uniform address -> broadcast
            ulonglong2 a01 = *(const ulonglong2*)&As[buf][kk][16*w];
            ulonglong2 a23 = *(const ulonglong2*)&As[buf][kk][16*w + 4];
            ulonglong2 a45 = *(const ulonglong2*)&As[buf][kk][16*w + 8];
            ulonglong2 a67 = *(const ulonglong2*)&As[buf][kk][16*w + 12];
            // B fragment: 4 natural (b[n],b[n+1]) pairs
            ulonglong2 b01 = *(const ulonglong2*)&Bs[buf][kk][l*8];
            ulonglong2 b23 = *(const ulonglong2*)&Bs[buf][kk][l*8 + 4];
            u64 av[8] = {a01.x, a01.y, a23.x, a23.y, a45.x, a45.y, a67.x, a67.y};
            u64 bv[4] = {b01.x, b01.y, b23.x, b23.y};
#pragma unroll
            for (int m = 0; m < 8; m++)
#pragma unroll
                for (int j = 0; j < 4; j++)
                    fma2(acc[m][j], av[m], bv[j]);
        }

        if (more) {
            const int nb = buf ^ 1;
            *(float2*)&As[nb][ak+0][2*arow] = make_float2(ra.x, ra.x);
            *(float2*)&As[nb][ak+1][2*arow] = make_float2(ra.y, ra.y);
            *(float2*)&As[nb][ak+2][2*arow] = make_float2(ra.z, ra.z);
            *(float2*)&As[nb][ak+3][2*arow] = make_float2(ra.w, ra.w);
            Bs[nb][bk+0][brow] = rb0.x; Bs[nb][bk+1][brow] = rb0.y;
            Bs[nb][bk+2][brow] = rb0.z; Bs[nb][bk+3][brow] = rb0.w;
            Bs[nb][bk+4][brow] = rb1.x; Bs[nb][bk+5][brow] = rb1.y;
            Bs[nb][bk+6][brow] = rb1.z; Bs[nb][bk+7][brow] = rb1.w;
            Bs[nb][bk+0][brow+128] = rb2.x; Bs[nb][bk+1][brow+128] = rb2.y;
            Bs[nb][bk+2][brow+128] = rb2.z; Bs[nb][bk+3][brow+128] = rb2.w;
            Bs[nb][bk+4][brow+128] = rb3.x; Bs[nb][bk+5][brow+128] = rb3.y;
            Bs[nb][bk+6][brow+128] = rb3.z; Bs[nb][bk+7][brow+128] = rb3.w;
            __syncthreads();
        }
        buf ^= 1;
    }

    // epilogue
    float4 bv0 = *(const float4*)&bias[n0 + l*8];
    float4 bv1 = *(const float4*)&bias[n0 + l*8 + 4];
    float bb[8] = {bv0.x, bv0.y, bv0.z, bv0.w, bv1.x, bv1.y, bv1.z, bv1.w};

#pragma unroll
    for (int m = 0; m < 8; m++) {
        float o[8];
#pragma unroll
        for (int j = 0; j < 4; j++) {
            float2 c = unpack2(acc[m][j]);
            o[2*j]   = c.x + bb[2*j];
            o[2*j+1] = c.y + bb[2*j+1];
        }
#pragma unroll
        for (int j = 0; j < 8; j++) {
            if (ACT == 1) o[j] = act_elu(o[j]);
            else if (ACT == 2) o[j] = act_softplus01(o[j]);
        }
        float* cp = &C[(m0 + w*8 + m) * (long)ldc + n0 + l*8];
        *(float4*)(cp)     = make_float4(o[0], o[1], o[2], o[3]);
        *(float4*)(cp + 4) = make_float4(o[4], o[5], o[6], o[7]);
    }
}

// =============================================================================
// step_fused: one GRU timestep.
//   Phase 1 (144 CTAs, split-K=3): ghp[ks] = h_prev @ Whh[:, kchunk]^T
//   device-wide arrival counter (all CTAs resident -> deadlock-free)
//   Phase 2: reduce partials + bhh, gates, write hidden[t].
// BM=64 (all of M), BN=128; warp w -> rows w*8..w*8+7, lane l -> cols l*4..l*4+3.
// =============================================================================
__global__ __launch_bounds__(256) void step_fused(
    const float* __restrict__ h_prev,   // [64, 2048]
    const float* __restrict__ W,        // [6144, 2048]
    const float* __restrict__ gx_t,     // [64, 6144]
    const float* __restrict__ bhh,      // [6144]
    float* __restrict__ ghp,            // [KSPLIT][64][6144]
    float* __restrict__ h_out,          // [64, 2048]
    unsigned int* __restrict__ counter)
{
    __shared__ __align__(16) float As[2][16][128];   // (a,a) pairs, 64 rows
    __shared__ __align__(16) float Bs[2][16][128];   // plain

    const int tid = threadIdx.x;
    const int w   = tid >> 5;
    const int l   = tid & 31;
    const long n0 = (long)blockIdx.x * 128;
    const int ks  = blockIdx.y;
    const int kbeg   = ks * 688;                 // 43*16
    const int ntiles = (ks == 2) ? 42 : 43;

    // loaders
    const int arow = tid & 63;
    const int ak   = (tid >> 6) * 4;
    const int brow = tid >> 1;
    const int bk   = (tid & 1) * 8;

    const float* Ap = h_prev + arow * (long)CH_ + kbeg + ak;
    const float* Wp = W + (n0 + brow) * (long)CH_ + kbeg + bk;

    u64 acc[8][2];
#pragma unroll
    for (int i = 0; i < 8; i++) { acc[i][0] = 0ull; acc[i][1] = 0ull; }

    float4 ra  = *(const float4*)Ap;
    float4 rb0 = *(const float4*)(Wp);
    float4 rb1 = *(const float4*)(Wp + 4);
    {
        *(float2*)&As[0][ak+0][2*arow] = make_float2(ra.x, ra.x);
        *(float2*)&As[0][ak+1][2*arow] = make_float2(ra.y, ra.y);
        *(float2*)&As[0][ak+2][2*arow] = make_float2(ra.z, ra.z);
        *(float2*)&As[0][ak+3][2*arow] = make_float2(ra.w, ra.w);
        Bs[0][bk+0][brow] = rb0.x; Bs[0][bk+1][brow] = rb0.y;
        Bs[0][bk+2][brow] = rb0.z; Bs[0][bk+3][brow] = rb0.w;
        Bs[0][bk+4][brow] = rb1.x; Bs[0][bk+5][brow] = rb1.y;
        Bs[0][bk+6][brow] = rb1.z; Bs[0][bk+7][brow] = rb1.w;
    }
    __syncthreads();

    int buf = 0;
    for (int kt = 0; kt < ntiles; kt++) {
        const bool more = (kt + 1 < ntiles);
        if (more) {
            const int o = (kt + 1) * 16;
            ra  = *(const float4*)(Ap + o);
            rb0 = *(const float4*)(Wp + o);
            rb1 = *(const float4*)(Wp + o + 4);
        }

#pragma unroll
        for (int kk = 0; kk < 16; kk++) {
            ulonglong2 a01 = *(const ulonglong2*)&As[buf][kk][16*w];
            ulonglong2 a23 = *(const ulonglong2*)&As[buf][kk][16*w + 4];
            ulonglong2 a45 = *(const ulonglong2*)&As[buf][kk][16*w + 8];
            ulonglong2 a67 = *(const ulonglong2*)&As[buf][kk][16*w + 12];
            ulonglong2 b01 = *(const ulonglong2*)&Bs[buf][kk][l*4];
            u64 av[8] = {a01.x, a01.y, a23.x, a23.y, a45.x, a45.y, a67.x, a67.y};
#pragma unroll
            for (int m = 0; m < 8; m++) {
                fma2(acc[m][0], av[m], b01.x);
                fma2(acc[m][1], av[m], b01.y);
            }
        }

        if (more) {
            const int nb = buf ^ 1;
            *(float2*)&As[nb][ak+0][2*arow] = make_float2(ra.x, ra.x);
            *(float2*)&As[nb][ak+1][2*arow] = make_float2(ra.y, ra.y);
            *(float2*)&As[nb][ak+2][2*arow] = make_float2(ra.z, ra.z);
            *(float2*)&As[nb][ak+3][2*arow] = make_float2(ra.w, ra.w);
            Bs[nb][bk+0][brow] = rb0.x; Bs[nb][bk+1][brow] = rb0.y;
            Bs[nb][bk+2][brow] = rb0.z; Bs[nb][bk+3][brow] = rb0.w;
            Bs[nb][bk+4][brow] = rb1.x; Bs[nb][bk+5][brow] = rb1.y;
            Bs[nb][bk+6][brow] = rb1.z; Bs[nb][bk+7][brow] = rb1.w;
            __syncthreads();
        }
        buf ^= 1;
    }

    // write partials
    {
        float* base = ghp + (size_t)ks * B_ * G_;
#pragma unroll
        for (int m = 0; m < 8; m++) {
            float2 c0 = unpack2(acc[m][0]);
            float2 c1 = unpack2(acc[m][1]);
            *(float4*)&base[(w*8 + m) * (long)G_ + n0 + l*4] =
                make_float4(c0.x, c0.y, c1.x, c1.y);
        }
    }

    // ---- device-wide arrival barrier (144 CTAs, all resident) ----
    __threadfence();
    __syncthreads();
    if (tid == 0) {
        atomicAdd(counter, 1u);
        while (atomicAdd(counter, 0u) < (unsigned)NCTA_STEP) { }
    }
    __syncthreads();

    // ---- phase 2: gates. CTAs 0..127 each handle 256 float4 items ----
    const int cta = blockIdx.y * 48 + blockIdx.x;
    const int idx4 = cta * 256 + tid;
    if (idx4 < B_ * CH_ / 4) {
        const int b  = idx4 >> 9;            // CH/4 = 512
        const int j4 = idx4 & 511;
        const long go = (long)b * G_ + j4 * 4;

        float4 xr = *(const float4*)(gx_t + go);
        float4 xz = *(const float4*)(gx_t + go + CH_);
        float4 xn = *(const float4*)(gx_t + go + 2*CH_);

        float4 hr = *(const float4*)(ghp + go);
        float4 hz = *(const float4*)(ghp + go + CH_);
        float4 hn = *(const float4*)(ghp + go + 2*CH_);
#pragma unroll
        for (int s = 1; s < KSPLIT; s++) {
            const float* p = ghp + (size_t)s * B_ * G_ + go;
            float4 a = *(const float4*)(p);
            float4 c = *(const float4*)(p + CH_);
            float4 d = *(const float4*)(p + 2*CH_);
            hr.x += a.x; hr.y += a.y; hr.z += a.z; hr.w += a.w;
            hz.x += c.x; hz.y += c.y; hz.z += c.z; hz.w += c.w;
            hn.x += d.x; hn.y += d.y; hn.z += d.z; hn.w += d.w;
        }
        float4 br = *(const float4*)(bhh + j4*4);
        float4 bz = *(const float4*)(bhh + CH_ + j4*4);
        float4 bn = *(const float4*)(bhh + 2*CH_ + j4*4);
        float4 hp = *(const float4*)(h_prev + (long)b * CH_ + j4*4);

        float xrv[4] = {xr.x, xr.y, xr.z, xr.w};
        float xzv[4] = {xz.x, xz.y, xz.z, xz.w};
        float xnv[4] = {xn.x, xn.y, xn.z, xn.w};
        float hrv[4] = {hr.x + br.x, hr.y + br.y, hr.z + br.z, hr.w + br.w};
        float hzv[4] = {hz.x + bz.x, hz.y + bz.y, hz.z + bz.z, hz.w + bz.w};
        float hnv[4] = {hn.x + bn.x, hn.y + bn.y, hn.z + bn.z, hn.w + bn.w};
        float hpv[4] = {hp.x, hp.y, hp.z, hp.w};
        float ov[4];
#pragma unroll
        for (int i = 0; i < 4; i++) {
            float r = 1.0f / (1.0f + expf(-(xrv[i] + hrv[i])));
            float z = 1.0f / (1.0f + expf(-(xzv[i] + hzv[i])));
            float n = tanhf(xnv[i] + r * hnv[i]);
            ov[i] = (1.0f - z) * n + z * hpv[i];
        }
        *(float4*)(h_out + (long)b * CH_ + j4*4) =
            make_float4(ov[0], ov[1], ov[2], ov[3]);
    }
}

// =============================================================================
// launch
// =============================================================================
extern "C" void kernel_launch(void* const* d_in, const int* in_sizes, int n_in,
                              void* d_out, int out_size)
{
    const float* x    = (const float*)d_in[0];
    const float* We   = (const float*)d_in[1];
    const float* be   = (const float*)d_in[2];
    const float* Wih  = (const float*)d_in[3];
    const float* bih  = (const float*)d_in[4];
    const float* Whh  = (const float*)d_in[5];
    const float* bhh  = (const float*)d_in[6];
    const float* Wmu  = (const float*)d_in[7];
    const float* bmu  = (const float*)d_in[8];
    const float* Wsig = (const float*)d_in[9];
    const float* bsig = (const float*)d_in[10];

    float* out        = (float*)d_out;
    float* out_mu     = out;
    float* out_sig    = out + (size_t)MB_ * DOUT_;
    float* out_hidden = out + (size_t)2 * MB_ * DOUT_;

    float *p_xe, *p_gx, *p_ghp, *p_h0;
    unsigned int* p_cnt;
    cudaGetSymbolAddress((void**)&p_xe, g_xe);
    cudaGetSymbolAddress((void**)&p_gx, g_gx);
    cudaGetSymbolAddress((void**)&p_ghp, g_ghp);
    cudaGetSymbolAddress((void**)&p_h0, g_h0);
    cudaGetSymbolAddress((void**)&p_cnt, g_cnt);

    dim3 blk(256);

    // 0) zero h0 + barrier counters (also shifts ncu parity onto step_fused)
    init_kernel<<<(B_ * CH_) / 256, blk>>>();

    // 1) xe = elu(x @ We^T + be)        [16384,1024], K=512
    gemm_big<1><<<dim3(H_/256, MB_/64), blk>>>(x, DIN_, We, DIN_, be,
                                               p_xe, H_, DIN_);
    // 2) gx = xe @ Wih^T + bih          [16384,6144], K=1024
    gemm_big<0><<<dim3(G_/256, MB_/64), blk>>>(p_xe, H_, Wih, H_, bih,
                                               p_gx, G_, H_);
    // 3) recurrence: one fused kernel per step
    for (int t = 0; t < T_; t++) {
        const float* hp = (t == 0) ? p_h0
                                   : out_hidden + (size_t)(t - 1) * B_ * CH_;
        step_fused<<<dim3(48, KSPLIT), blk>>>(
            hp, Whh, p_gx + (size_t)t * B_ * G_, bhh, p_ghp,
            out_hidden + (size_t)t * B_ * CH_, p_cnt + t);
    }
    // 4) mu = elu(h_mu @ Wmu^T + bmu)   [16384,512], K=1024
    gemm_big<1><<<dim3(DOUT_/256, MB_/64), blk>>>(out_hidden, CH_, Wmu, H_, bmu,
                                                  out_mu, DOUT_, H_);
    // 5) sig = softplus(...) + 0.1
    gemm_big<2><<<dim3(DOUT_/256, MB_/64), blk>>>(out_hidden + H_, CH_, Wsig, H_, bsig,
                                                  out_sig, DOUT_, H_);
}

// round 6
// speedup vs baseline: 2.6270x; 1.6420x over previous
#include <cuda_runtime.h>
#include <cuda_bf16.h>
#include <cstdint>
#include <cstddef>

#define T_    256
#define B_    64
#define DIN_  512
#define H_    1024
#define CH_   2048
#define G_    6144
#define DOUT_ 512
#define MB_   (T_*B_)
#define KSPLIT 8
#define NCTA_STEP 128

// ---------------- scratch (device globals) ----------------------------------
__device__ float g_xe[(size_t)MB_ * H_];
__device__ float g_gx[(size_t)MB_ * G_];
__device__ float g_ghp[(size_t)KSPLIT * B_ * G_];   // 12.6 MB partials
__device__ float g_h0[(size_t)B_ * CH_];
__device__ __nv_bfloat16 g_whh_hi[(size_t)G_ * CH_];
__device__ __nv_bfloat16 g_whh_lo[(size_t)G_ * CH_];
__device__ __nv_bfloat16 g_hh[2][(size_t)B_ * CH_];
__device__ __nv_bfloat16 g_hl[2][(size_t)B_ * CH_];
__device__ unsigned int g_cnt[T_];

typedef unsigned long long u64;

__device__ __forceinline__ void fma2(u64& a, u64 x, u64 y) {
    asm("fma.rn.f32x2 %0, %1, %2, %0;" : "+l"(a) : "l"(x), "l"(y));
}
__device__ __forceinline__ float2 unpack2(u64 v) {
    float2 f;
    asm("mov.b64 {%0, %1}, %2;" : "=f"(f.x), "=f"(f.y) : "l"(v));
    return f;
}
__device__ __forceinline__ float act_elu(float v) {
    return v > 0.0f ? v : expm1f(v);
}
__device__ __forceinline__ float act_softplus01(float v) {
    return fmaxf(v, 0.0f) + log1pf(expf(-fabsf(v))) + 0.1f;
}

// ---------------- sm_80-era primitives (legal on plain compute_103) ----------
__device__ __forceinline__ uint32_t smem_u32(const void* p) {
    uint32_t a;
    asm("{ .reg .u64 t; cvta.to.shared.u64 t, %1; cvt.u32.u64 %0, t; }"
        : "=r"(a) : "l"(p));
    return a;
}
__device__ __forceinline__ void cp16(uint32_t dst, const void* src) {
    asm volatile("cp.async.cg.shared.global [%0], [%1], 16;"
                 :: "r"(dst), "l"(src) : "memory");
}
__device__ __forceinline__ void ldm4(uint32_t addr, uint32_t r[4]) {
    asm volatile("ldmatrix.sync.aligned.m8n8.x4.shared.b16 {%0,%1,%2,%3}, [%4];"
                 : "=r"(r[0]), "=r"(r[1]), "=r"(r[2]), "=r"(r[3]) : "r"(addr));
}
__device__ __forceinline__ void mma16816(float d[4], const uint32_t a[4],
                                         uint32_t b0, uint32_t b1) {
    asm volatile(
        "mma.sync.aligned.m16n8k16.row.col.f32.bf16.bf16.f32 "
        "{%0,%1,%2,%3}, {%4,%5,%6,%7}, {%8,%9}, {%0,%1,%2,%3};"
        : "+f"(d[0]), "+f"(d[1]), "+f"(d[2]), "+f"(d[3])
        : "r"(a[0]), "r"(a[1]), "r"(a[2]), "r"(a[3]), "r"(b0), "r"(b1));
}

// SMEM layout for step_mma (dynamic):
//  Bh [64 rows x 528 B]   @ 0
//  Bl [64 rows x 528 B]   @ 33792
//  A stages: 2 x (hi 128x80 + lo 128x80) @ 67584
#define BSM_H    0
#define BSM_L    33792
#define ASM_BASE 67584
#define A_STAGE  20480
#define SM_DYN   (ASM_BASE + 2 * A_STAGE)   // 108544

// =============================================================================
__global__ void init_kernel() {
    int idx = blockIdx.x * 256 + threadIdx.x;          // grid 512
    g_h0[idx] = 0.0f;
    g_hh[0][idx] = __float2bfloat16(0.0f);
    g_hl[0][idx] = __float2bfloat16(0.0f);
    if (idx < T_) g_cnt[idx] = 0u;
}

__global__ void split_whh(const float* __restrict__ W) {
    size_t i = ((size_t)blockIdx.x * 256 + threadIdx.x) * 4;   // grid 12288
    float4 w = *(const float4*)(W + i);
    float f[4] = {w.x, w.y, w.z, w.w};
#pragma unroll
    for (int k = 0; k < 4; k++) {
        __nv_bfloat16 hi = __float2bfloat16(f[k]);
        g_whh_hi[i + k] = hi;
        g_whh_lo[i + k] = __float2bfloat16(f[k] - __bfloat162float(hi));
    }
}

// =============================================================================
// gemm_big (proven): C[M,N] = act(A @ W^T + bias), BM=64 BN=256 BK=16
// =============================================================================
template <int ACT>
__global__ __launch_bounds__(256) void gemm_big(
    const float* __restrict__ A, int lda,
    const float* __restrict__ W, int ldw,
    const float* __restrict__ bias,
    float* __restrict__ C, int ldc, int K)
{
    __shared__ __align__(16) float As[2][16][128];
    __shared__ __align__(16) float Bs[2][16][256];

    const int tid = threadIdx.x;
    const int w   = tid >> 5;
    const int l   = tid & 31;
    const long m0 = (long)blockIdx.y * 64;
    const long n0 = (long)blockIdx.x * 256;
    const int arow = tid & 63;
    const int ak   = (tid >> 6) * 4;
    const int brow = tid >> 1;
    const int bk   = (tid & 1) * 8;

    const float* Ap  = A + (m0 + arow) * (long)lda + ak;
    const float* Wp0 = W + (n0 + brow) * (long)ldw + bk;
    const float* Wp1 = W + (n0 + brow + 128) * (long)ldw + bk;

    u64 acc[8][4];
#pragma unroll
    for (int i = 0; i < 8; i++)
#pragma unroll
        for (int j = 0; j < 4; j++) acc[i][j] = 0ull;

    const int ntiles = K >> 4;
    float4 ra  = *(const float4*)Ap;
    float4 rb0 = *(const float4*)(Wp0);
    float4 rb1 = *(const float4*)(Wp0 + 4);
    float4 rb2 = *(const float4*)(Wp1);
    float4 rb3 = *(const float4*)(Wp1 + 4);
    {
        *(float2*)&As[0][ak+0][2*arow] = make_float2(ra.x, ra.x);
        *(float2*)&As[0][ak+1][2*arow] = make_float2(ra.y, ra.y);
        *(float2*)&As[0][ak+2][2*arow] = make_float2(ra.z, ra.z);
        *(float2*)&As[0][ak+3][2*arow] = make_float2(ra.w, ra.w);
        Bs[0][bk+0][brow] = rb0.x; Bs[0][bk+1][brow] = rb0.y;
        Bs[0][bk+2][brow] = rb0.z; Bs[0][bk+3][brow] = rb0.w;
        Bs[0][bk+4][brow] = rb1.x; Bs[0][bk+5][brow] = rb1.y;
        Bs[0][bk+6][brow] = rb1.z; Bs[0][bk+7][brow] = rb1.w;
        Bs[0][bk+0][brow+128] = rb2.x; Bs[0][bk+1][brow+128] = rb2.y;
        Bs[0][bk+2][brow+128] = rb2.z; Bs[0][bk+3][brow+128] = rb2.w;
        Bs[0][bk+4][brow+128] = rb3.x; Bs[0][bk+5][brow+128] = rb3.y;
        Bs[0][bk+6][brow+128] = rb3.z; Bs[0][bk+7][brow+128] = rb3.w;
    }
    __syncthreads();

    int buf = 0;
    for (int kt = 0; kt < ntiles; kt++) {
        const bool more = (kt + 1 < ntiles);
        if (more) {
            const int o = (kt + 1) * 16;
            ra  = *(const float4*)(Ap + o);
            rb0 = *(const float4*)(Wp0 + o);
            rb1 = *(const float4*)(Wp0 + o + 4);
            rb2 = *(const float4*)(Wp1 + o);
            rb3 = *(const float4*)(Wp1 + o + 4);
        }
#pragma unroll
        for (int kk = 0; kk < 16; kk++) {
            ulonglong2 a01 = *(const ulonglong2*)&As[buf][kk][16*w];
            ulonglong2 a23 = *(const ulonglong2*)&As[buf][kk][16*w + 4];
            ulonglong2 a45 = *(const ulonglong2*)&As[buf][kk][16*w + 8];
            ulonglong2 a67 = *(const ulonglong2*)&As[buf][kk][16*w + 12];
            ulonglong2 b01 = *(const ulonglong2*)&Bs[buf][kk][l*8];
            ulonglong2 b23 = *(const ulonglong2*)&Bs[buf][kk][l*8 + 4];
            u64 av[8] = {a01.x, a01.y, a23.x, a23.y, a45.x, a45.y, a67.x, a67.y};
            u64 bv[4] = {b01.x, b01.y, b23.x, b23.y};
#pragma unroll
            for (int m = 0; m < 8; m++)
#pragma unroll
                for (int j = 0; j < 4; j++)
                    fma2(acc[m][j], av[m], bv[j]);
        }
        if (more) {
            const int nb = buf ^ 1;
            *(float2*)&As[nb][ak+0][2*arow] = make_float2(ra.x, ra.x);
            *(float2*)&As[nb][ak+1][2*arow] = make_float2(ra.y, ra.y);
            *(float2*)&As[nb][ak+2][2*arow] = make_float2(ra.z, ra.z);
            *(float2*)&As[nb][ak+3][2*arow] = make_float2(ra.w, ra.w);
            Bs[nb][bk+0][brow] = rb0.x; Bs[nb][bk+1][brow] = rb0.y;
            Bs[nb][bk+2][brow] = rb0.z; Bs[nb][bk+3][brow] = rb0.w;
            Bs[nb][bk+4][brow] = rb1.x; Bs[nb][bk+5][brow] = rb1.y;
            Bs[nb][bk+6][brow] = rb1.z; Bs[nb][bk+7][brow] = rb1.w;
            Bs[nb][bk+0][brow+128] = rb2.x; Bs[nb][bk+1][brow+128] = rb2.y;
            Bs[nb][bk+2][brow+128] = rb2.z; Bs[nb][bk+3][brow+128] = rb2.w;
            Bs[nb][bk+4][brow+128] = rb3.x; Bs[nb][bk+5][brow+128] = rb3.y;
            Bs[nb][bk+6][brow+128] = rb3.z; Bs[nb][bk+7][brow+128] = rb3.w;
            __syncthreads();
        }
        buf ^= 1;
    }

    float4 bv0 = *(const float4*)&bias[n0 + l*8];
    float4 bv1 = *(const float4*)&bias[n0 + l*8 + 4];
    float bb[8] = {bv0.x, bv0.y, bv0.z, bv0.w, bv1.x, bv1.y, bv1.z, bv1.w};
#pragma unroll
    for (int m = 0; m < 8; m++) {
        float o[8];
#pragma unroll
        for (int j = 0; j < 4; j++) {
            float2 c = unpack2(acc[m][j]);
            o[2*j]   = c.x + bb[2*j];
            o[2*j+1] = c.y + bb[2*j+1];
        }
#pragma unroll
        for (int j = 0; j < 8; j++) {
            if (ACT == 1) o[j] = act_elu(o[j]);
            else if (ACT == 2) o[j] = act_softplus01(o[j]);
        }
        float* cp = &C[(m0 + w*8 + m) * (long)ldc + n0 + l*8];
        *(float4*)(cp)     = make_float4(o[0], o[1], o[2], o[3]);
        *(float4*)(cp + 4) = make_float4(o[4], o[5], o[6], o[7]);
    }
}

// =============================================================================
// step_mma: one GRU timestep via HMMA (mma.sync bf16, 3-term hi/lo split).
// grid (16 j-blocks, 8 k-splits) = 128 CTAs (all resident), 256 threads.
// Phase 1: partials ghp[ks][b][g] ; device barrier ; Phase 2: fused gates.
// =============================================================================
__global__ __launch_bounds__(256, 1) void step_mma(
    const __nv_bfloat16* __restrict__ whh_hi,
    const __nv_bfloat16* __restrict__ whh_lo,
    const __nv_bfloat16* __restrict__ hh_in,
    const __nv_bfloat16* __restrict__ hl_in,
    const float* __restrict__ gx_t,     // [64, 6144]
    const float* __restrict__ bhh,
    const float* __restrict__ h_prev,   // [64, 2048] fp32
    float* __restrict__ ghp,            // [KSPLIT][64][6144]
    float* __restrict__ h_out,
    __nv_bfloat16* __restrict__ hh_out,
    __nv_bfloat16* __restrict__ hl_out,
    unsigned int* __restrict__ counter)
{
    extern __shared__ __align__(16) char smem[];
    const uint32_t sb = smem_u32(smem);
    const int tid = threadIdx.x;
    const int w = tid >> 5, l = tid & 31;
    const int j0 = blockIdx.x * 128;
    const int ks = blockIdx.y;
    const int k0 = ks * 256;
    const int wm = w >> 1, wn = w & 1;

    // ---- B chunk (h hi/lo) [64 x 256] -> smem rows padded to 528 B ----
#pragma unroll
    for (int i = 0; i < 8; i++) {
        int o = i * 256 + tid;
        int row = o >> 5, c = o & 31;
        cp16(sb + BSM_H + row * 528 + c * 16, hh_in + (size_t)row * CH_ + k0 + c * 8);
        cp16(sb + BSM_L + row * 528 + c * 16, hl_in + (size_t)row * CH_ + k0 + c * 8);
    }

    // A stage loader: stage s -> gate = s>>3, kt = s&7 (32 k per stage)
    auto load_a = [&](int slot, int s) {
        const int gate = s >> 3, kt = s & 7;
        const uint32_t dst = sb + ASM_BASE + slot * A_STAGE;
#pragma unroll
        for (int i = 0; i < 2; i++) {
            int o = i * 256 + tid;
            int row = o >> 2, c = o & 3;
            size_t off = (size_t)(gate * CH_ + j0 + row) * CH_ + k0 + kt * 32 + c * 8;
            cp16(dst + row * 80 + c * 16, whh_hi + off);
            cp16(dst + 10240 + row * 80 + c * 16, whh_lo + off);
        }
        asm volatile("cp.async.commit_group;" ::: "memory");
    };
    load_a(0, 0);   // group 0 also covers the B loads above
    load_a(1, 1);

    // ldmatrix lane offsets (canonical x4 mappings)
    const uint32_t aoff = (uint32_t)((l & 15) * 80 + (l >> 4) * 16);
    const uint32_t boff = (uint32_t)((wn * 32 + (l & 7) + ((l >> 4) & 1) * 8) * 528
                                     + ((l >> 3) & 1) * 16);

    float acc[2][4][4];
#pragma unroll
    for (int a = 0; a < 2; a++)
#pragma unroll
        for (int b = 0; b < 4; b++)
#pragma unroll
            for (int c = 0; c < 4; c++) acc[a][b][c] = 0.0f;

    for (int s = 0; s < 24; s++) {
        const int slot = s & 1;
        const int kt = s & 7;
        if (s < 23) asm volatile("cp.async.wait_group 1;" ::: "memory");
        else        asm volatile("cp.async.wait_group 0;" ::: "memory");
        __syncthreads();

        const uint32_t aH = sb + ASM_BASE + slot * A_STAGE + (uint32_t)(wm * 2560) + aoff;
        const uint32_t bHb = sb + BSM_H + boff + kt * 64;
        const uint32_t bLb = sb + BSM_L + boff + kt * 64;

#pragma unroll
        for (int k16 = 0; k16 < 2; k16++) {
            uint32_t ah[2][4], al[2][4], bh[2][4], bl[2][4];
#pragma unroll
            for (int mf = 0; mf < 2; mf++) {
                ldm4(aH + mf * 1280 + k16 * 32, ah[mf]);
                ldm4(aH + 10240 + mf * 1280 + k16 * 32, al[mf]);
            }
#pragma unroll
            for (int nf = 0; nf < 2; nf++) {
                ldm4(bHb + nf * 8448 + k16 * 32, bh[nf]);
                ldm4(bLb + nf * 8448 + k16 * 32, bl[nf]);
            }
#pragma unroll
            for (int mf = 0; mf < 2; mf++)
#pragma unroll
                for (int nf = 0; nf < 4; nf++) {
                    const uint32_t* bp = bh[nf >> 1];
                    const uint32_t* lp = bl[nf >> 1];
                    uint32_t b0 = bp[(nf & 1) * 2], b1 = bp[(nf & 1) * 2 + 1];
                    uint32_t c0 = lp[(nf & 1) * 2], c1 = lp[(nf & 1) * 2 + 1];
                    mma16816(acc[mf][nf], ah[mf], b0, b1);   // hi*hi
                    mma16816(acc[mf][nf], ah[mf], c0, c1);   // hi*lo
                    mma16816(acc[mf][nf], al[mf], b0, b1);   // lo*hi
                }
        }
        __syncthreads();
        if (s + 2 < 24) load_a(slot, s + 2);

        if (kt == 7) {   // gate finished -> write partials, reset acc
            const int gate = s >> 3;
            float* base = ghp + (size_t)ks * B_ * G_;
            const int jb = gate * CH_ + j0 + wm * 32 + (l >> 2);
            const int bb = wn * 32 + (l & 3) * 2;
#pragma unroll
            for (int mf = 0; mf < 2; mf++)
#pragma unroll
                for (int nf = 0; nf < 4; nf++) {
                    const int j = jb + mf * 16;
                    const int b = bb + nf * 8;
                    base[(size_t)b * G_ + j]           = acc[mf][nf][0];
                    base[(size_t)(b + 1) * G_ + j]     = acc[mf][nf][1];
                    base[(size_t)b * G_ + j + 8]       = acc[mf][nf][2];
                    base[(size_t)(b + 1) * G_ + j + 8] = acc[mf][nf][3];
                    acc[mf][nf][0] = acc[mf][nf][1] = 0.0f;
                    acc[mf][nf][2] = acc[mf][nf][3] = 0.0f;
                }
        }
    }

    // ---- device-wide arrival barrier (128 CTAs, all resident) ----
    __threadfence();
    __syncthreads();
    if (tid == 0) {
        atomicAdd(counter, 1u);
        while (atomicAdd(counter, 0u) < (unsigned)NCTA_STEP) { }
    }
    __syncthreads();

    // ---- phase 2: reduce 8 partials + gates ----
    const int cta = blockIdx.y * 16 + blockIdx.x;
    const int idx4 = cta * 256 + tid;            // exactly B_*CH_/4 items
    {
        const int b  = idx4 >> 9;
        const int j4 = idx4 & 511;
        const long go = (long)b * G_ + j4 * 4;

        float4 xr = *(const float4*)(gx_t + go);
        float4 xz = *(const float4*)(gx_t + go + CH_);
        float4 xn = *(const float4*)(gx_t + go + 2*CH_);

        float4 hr = *(const float4*)(ghp + go);
        float4 hz = *(const float4*)(ghp + go + CH_);
        float4 hn = *(const float4*)(ghp + go + 2*CH_);
#pragma unroll
        for (int s = 1; s < KSPLIT; s++) {
            const float* p = ghp + (size_t)s * B_ * G_ + go;
            float4 a = *(const float4*)(p);
            float4 c = *(const float4*)(p + CH_);
            float4 d = *(const float4*)(p + 2*CH_);
            hr.x += a.x; hr.y += a.y; hr.z += a.z; hr.w += a.w;
            hz.x += c.x; hz.y += c.y; hz.z += c.z; hz.w += c.w;
            hn.x += d.x; hn.y += d.y; hn.z += d.z; hn.w += d.w;
        }
        float4 br = *(const float4*)(bhh + j4*4);
        float4 bz = *(const float4*)(bhh + CH_ + j4*4);
        float4 bn = *(const float4*)(bhh + 2*CH_ + j4*4);
        float4 hp = *(const float4*)(h_prev + (long)b * CH_ + j4*4);

        float xrv[4] = {xr.x, xr.y, xr.z, xr.w};
        float xzv[4] = {xz.x, xz.y, xz.z, xz.w};
        float xnv[4] = {xn.x, xn.y, xn.z, xn.w};
        float hrv[4] = {hr.x + br.x, hr.y + br.y, hr.z + br.z, hr.w + br.w};
        float hzv[4] = {hz.x + bz.x, hz.y + bz.y, hz.z + bz.z, hz.w + bz.w};
        float hnv[4] = {hn.x + bn.x, hn.y + bn.y, hn.z + bn.z, hn.w + bn.w};
        float hpv[4] = {hp.x, hp.y, hp.z, hp.w};
        float ov[4];
#pragma unroll
        for (int i = 0; i < 4; i++) {
            float r = 1.0f / (1.0f + expf(-(xrv[i] + hrv[i])));
            float z = 1.0f / (1.0f + expf(-(xzv[i] + hzv[i])));
            float n = tanhf(xnv[i] + r * hnv[i]);
            ov[i] = (1.0f - z) * n + z * hpv[i];
        }
        const long ho = (long)b * CH_ + j4 * 4;
        *(float4*)(h_out + ho) = make_float4(ov[0], ov[1], ov[2], ov[3]);
#pragma unroll
        for (int i = 0; i < 4; i++) {
            __nv_bfloat16 hi = __float2bfloat16(ov[i]);
            hh_out[ho + i] = hi;
            hl_out[ho + i] = __float2bfloat16(ov[i] - __bfloat162float(hi));
        }
    }
}

// =============================================================================
extern "C" void kernel_launch(void* const* d_in, const int* in_sizes, int n_in,
                              void* d_out, int out_size)
{
    const float* x    = (const float*)d_in[0];
    const float* We   = (const float*)d_in[1];
    const float* be   = (const float*)d_in[2];
    const float* Wih  = (const float*)d_in[3];
    const float* bih  = (const float*)d_in[4];
    const float* Whh  = (const float*)d_in[5];
    const float* bhh  = (const float*)d_in[6];
    const float* Wmu  = (const float*)d_in[7];
    const float* bmu  = (const float*)d_in[8];
    const float* Wsig = (const float*)d_in[9];
    const float* bsig = (const float*)d_in[10];

    float* out        = (float*)d_out;
    float* out_mu     = out;
    float* out_sig    = out + (size_t)MB_ * DOUT_;
    float* out_hidden = out + (size_t)2 * MB_ * DOUT_;

    float *p_xe, *p_gx, *p_ghp, *p_h0;
    __nv_bfloat16 *p_whh_hi, *p_whh_lo, *p_hh, *p_hl;
    unsigned int* p_cnt;
    cudaGetSymbolAddress((void**)&p_xe, g_xe);
    cudaGetSymbolAddress((void**)&p_gx, g_gx);
    cudaGetSymbolAddress((void**)&p_ghp, g_ghp);
    cudaGetSymbolAddress((void**)&p_h0, g_h0);
    cudaGetSymbolAddress((void**)&p_whh_hi, g_whh_hi);
    cudaGetSymbolAddress((void**)&p_whh_lo, g_whh_lo);
    cudaGetSymbolAddress((void**)&p_hh, g_hh);
    cudaGetSymbolAddress((void**)&p_hl, g_hl);
    cudaGetSymbolAddress((void**)&p_cnt, g_cnt);
    const size_t HB = (size_t)B_ * CH_;

    cudaFuncSetAttribute(step_mma, cudaFuncAttributeMaxDynamicSharedMemorySize, SM_DYN);

    dim3 blk(256);
    init_kernel<<<512, blk>>>();
    split_whh<<<(int)((size_t)G_ * CH_ / 1024), blk>>>(Whh);

    gemm_big<1><<<dim3(H_/256, MB_/64), blk>>>(x, DIN_, We, DIN_, be, p_xe, H_, DIN_);
    gemm_big<0><<<dim3(G_/256, MB_/64), blk>>>(p_xe, H_, Wih, H_, bih, p_gx, G_, H_);

    for (int t = 0; t < T_; t++) {
        const float* hp = (t == 0) ? p_h0
                                   : out_hidden + (size_t)(t - 1) * B_ * CH_;
        const int bi = t & 1, bo = (t + 1) & 1;
        step_mma<<<dim3(16, KSPLIT), blk, SM_DYN>>>(
            p_whh_hi, p_whh_lo, p_hh + bi * HB, p_hl + bi * HB,
            p_gx + (size_t)t * B_ * G_, bhh, hp, p_ghp,
            out_hidden + (size_t)t * B_ * CH_,
            p_hh + bo * HB, p_hl + bo * HB, p_cnt + t);
    }

    gemm_big<1><<<dim3(DOUT_/256, MB_/64), blk>>>(out_hidden, CH_, Wmu, H_, bmu,
                                                  out_mu, DOUT_, H_);
    gemm_big<2><<<dim3(DOUT_/256, MB_/64), blk>>>(out_hidden + H_, CH_, Wsig, H_, bsig,
                                                  out_sig, DOUT_, H_);
}

// round 8
// speedup vs baseline: 4.2553x; 1.6198x over previous
#include <cuda_runtime.h>
#include <cuda_bf16.h>
#include <cstdint>
#include <cstddef>

#define T_    256
#define B_    64
#define DIN_  512
#define H_    1024
#define CH_   2048
#define G_    6144
#define DOUT_ 512
#define MB_   (T_*B_)
#define KSPLIT 8
#define NCTA_STEP 128

typedef __nv_bfloat16 bf16;
typedef unsigned long long u64;

// ---------------- scratch (device globals) ----------------------------------
__device__ float g_gx[(size_t)MB_ * G_];
__device__ float g_ghp[(size_t)KSPLIT * B_ * G_];
__device__ float g_h0[(size_t)B_ * CH_];
__device__ bf16 g_xh[(size_t)MB_ * DIN_],  g_xl[(size_t)MB_ * DIN_];
__device__ bf16 g_xeh[(size_t)MB_ * H_],   g_xel[(size_t)MB_ * H_];
__device__ bf16 g_weh[(size_t)H_ * DIN_],  g_wel[(size_t)H_ * DIN_];
__device__ bf16 g_wihh[(size_t)G_ * H_],   g_wihl[(size_t)G_ * H_];
__device__ bf16 g_whh_hi[(size_t)G_ * CH_], g_whh_lo[(size_t)G_ * CH_];
__device__ bf16 g_wmuh[(size_t)DOUT_ * H_], g_wmul[(size_t)DOUT_ * H_];
__device__ bf16 g_wsgh[(size_t)DOUT_ * H_], g_wsgl[(size_t)DOUT_ * H_];
__device__ bf16 g_hhA[(size_t)MB_ * CH_],  g_hlA[(size_t)MB_ * CH_];
__device__ bf16 g_hh0[(size_t)B_ * CH_],   g_hl0[(size_t)B_ * CH_];
__device__ unsigned int g_cnt[T_];

__device__ __forceinline__ float act_elu(float v) {
    return v > 0.0f ? v : expm1f(v);
}
__device__ __forceinline__ float act_softplus01(float v) {
    return fmaxf(v, 0.0f) + log1pf(expf(-fabsf(v))) + 0.1f;
}

// ---------------- sm_80-era primitives ---------------------------------------
__device__ __forceinline__ uint32_t smem_u32(const void* p) {
    uint32_t a;
    asm("{ .reg .u64 t; cvta.to.shared.u64 t, %1; cvt.u32.u64 %0, t; }"
        : "=r"(a) : "l"(p));
    return a;
}
__device__ __forceinline__ void cp16(uint32_t dst, const void* src) {
    asm volatile("cp.async.cg.shared.global [%0], [%1], 16;"
                 :: "r"(dst), "l"(src) : "memory");
}
__device__ __forceinline__ void ldm4(uint32_t addr, uint32_t r[4]) {
    asm volatile("ldmatrix.sync.aligned.m8n8.x4.shared.b16 {%0,%1,%2,%3}, [%4];"
                 : "=r"(r[0]), "=r"(r[1]), "=r"(r[2]), "=r"(r[3]) : "r"(addr));
}
__device__ __forceinline__ void mma16816(float d[4], const uint32_t a[4],
                                         uint32_t b0, uint32_t b1) {
    asm volatile(
        "mma.sync.aligned.m16n8k16.row.col.f32.bf16.bf16.f32 "
        "{%0,%1,%2,%3}, {%4,%5,%6,%7}, {%8,%9}, {%0,%1,%2,%3};"
        : "+f"(d[0]), "+f"(d[1]), "+f"(d[2]), "+f"(d[3])
        : "r"(a[0]), "r"(a[1]), "r"(a[2]), "r"(a[3]), "r"(b0), "r"(b1));
}

// =============================================================================
__global__ void init_kernel() {
    int idx = blockIdx.x * 256 + threadIdx.x;          // grid 512
    g_h0[idx] = 0.0f;
    g_hh0[idx] = __float2bfloat16(0.0f);
    g_hl0[idx] = __float2bfloat16(0.0f);
    if (idx < T_) g_cnt[idx] = 0u;
}

// split fp32 -> bf16 hi + lo (n divisible by 1024; grid = n/1024)
__global__ void split_f2b(const float* __restrict__ src,
                          bf16* __restrict__ hi, bf16* __restrict__ lo) {
    size_t i = ((size_t)blockIdx.x * 256 + threadIdx.x) * 4;
    float4 w = *(const float4*)(src + i);
    float f[4] = {w.x, w.y, w.z, w.w};
#pragma unroll
    for (int k = 0; k < 4; k++) {
        bf16 h = __float2bfloat16(f[k]);
        hi[i + k] = h;
        lo[i + k] = __float2bfloat16(f[k] - __bfloat162float(h));
    }
}

// =============================================================================
// gemm_tc: C[M,N] = act(A[M,K] @ W[N,K]^T + bias)  via bf16 HMMA 3-term split.
// BM=BN=128, BK=32, 256 threads (warp grid 4m x 2n, warp tile 32x64).
// SPLIT=1: write Ch/Cl bf16 hi/lo instead of fp32 C.
// =============================================================================
#define GT_TILE  10240        // 128 rows x 80 B
#define GT_STAGE (4*GT_TILE)  // Ah, Al, Wh, Wl
#define GT_SMEM  (2*GT_STAGE) // 81920

template <int ACT, int SPLIT>
__global__ __launch_bounds__(256) void gemm_tc(
    const bf16* __restrict__ Ah, const bf16* __restrict__ Al, int lda,
    const bf16* __restrict__ Wh, const bf16* __restrict__ Wl, int ldw,
    const float* __restrict__ bias,
    float* __restrict__ C, int ldc,
    bf16* __restrict__ Ch, bf16* __restrict__ Cl,
    int K)
{
    extern __shared__ __align__(16) char smem[];
    const uint32_t sb = smem_u32(smem);
    const int tid = threadIdx.x;
    const int w = tid >> 5, l = tid & 31;
    const int wm = w >> 1, wn = w & 1;
    const long m0 = (long)blockIdx.y * 128;
    const long n0 = (long)blockIdx.x * 128;

    auto load_stage = [&](int slot, int kt) {
        const uint32_t dst = sb + slot * GT_STAGE;
        const int k0 = kt * 32;
#pragma unroll
        for (int i = 0; i < 2; i++) {
            int o = i * 256 + tid;
            int row = o >> 2, c = o & 3;
            size_t ao = (m0 + row) * (size_t)lda + k0 + c * 8;
            size_t wo = (n0 + row) * (size_t)ldw + k0 + c * 8;
            uint32_t d = dst + row * 80 + c * 16;
            cp16(d,               Ah + ao);
            cp16(d + GT_TILE,     Al + ao);
            cp16(d + 2*GT_TILE,   Wh + wo);
            cp16(d + 3*GT_TILE,   Wl + wo);
        }
        asm volatile("cp.async.commit_group;" ::: "memory");
    };

    const int nst = K >> 5;
    load_stage(0, 0);
    load_stage(1, 1);

    const uint32_t aoff = (uint32_t)((l & 15) * 80 + (l >> 4) * 16);
    const uint32_t woff = (uint32_t)(((l & 7) + ((l >> 4) & 1) * 8) * 80
                                     + ((l >> 3) & 1) * 16);

    float acc[2][8][4];
#pragma unroll
    for (int a = 0; a < 2; a++)
#pragma unroll
        for (int b = 0; b < 8; b++)
#pragma unroll
            for (int c = 0; c < 4; c++) acc[a][b][c] = 0.0f;

    for (int s = 0; s < nst; s++) {
        const int slot = s & 1;
        if (s + 1 < nst) asm volatile("cp.async.wait_group 1;" ::: "memory");
        else             asm volatile("cp.async.wait_group 0;" ::: "memory");
        __syncthreads();

        const uint32_t stg = sb + slot * GT_STAGE;
        const uint32_t aH = stg + wm * 2560 + aoff;             // hi A
        const uint32_t wH = stg + 2*GT_TILE + wn * 5120 + woff; // hi W

#pragma unroll
        for (int k16 = 0; k16 < 2; k16++) {
            uint32_t ah[2][4], al[2][4], wh[4][4], wl[4][4];
#pragma unroll
            for (int mf = 0; mf < 2; mf++) {
                ldm4(aH + mf * 1280 + k16 * 32, ah[mf]);
                ldm4(aH + GT_TILE + mf * 1280 + k16 * 32, al[mf]);
            }
#pragma unroll
            for (int g = 0; g < 4; g++) {
                ldm4(wH + g * 1280 + k16 * 32, wh[g]);
                ldm4(wH + GT_TILE + g * 1280 + k16 * 32, wl[g]);
            }
#pragma unroll
            for (int mf = 0; mf < 2; mf++)
#pragma unroll
                for (int nf = 0; nf < 8; nf++) {
                    const uint32_t* bp = wh[nf >> 1];
                    const uint32_t* lp = wl[nf >> 1];
                    uint32_t b0 = bp[(nf & 1) * 2], b1 = bp[(nf & 1) * 2 + 1];
                    uint32_t c0 = lp[(nf & 1) * 2], c1 = lp[(nf & 1) * 2 + 1];
                    mma16816(acc[mf][nf], ah[mf], b0, b1);
                    mma16816(acc[mf][nf], ah[mf], c0, c1);
                    mma16816(acc[mf][nf], al[mf], b0, b1);
                }
        }
        __syncthreads();
        if (s + 2 < nst) load_stage(slot, s + 2);
    }

    // epilogue
    const int r0 = wm * 32 + (l >> 2);
    const int c0 = wn * 64 + (l & 3) * 2;
#pragma unroll
    for (int mf = 0; mf < 2; mf++)
#pragma unroll
        for (int nf = 0; nf < 8; nf++) {
            const long col = n0 + c0 + nf * 8;
            const float b0 = bias[col], b1 = bias[col + 1];
#pragma unroll
            for (int rr = 0; rr < 2; rr++) {
                const long row = m0 + r0 + mf * 16 + rr * 8;
                float v0 = acc[mf][nf][rr * 2]     + b0;
                float v1 = acc[mf][nf][rr * 2 + 1] + b1;
                if (ACT == 1) { v0 = act_elu(v0); v1 = act_elu(v1); }
                else if (ACT == 2) { v0 = act_softplus01(v0); v1 = act_softplus01(v1); }
                if (SPLIT) {
                    bf16 h0 = __float2bfloat16(v0);
                    bf16 h1 = __float2bfloat16(v1);
                    *(__nv_bfloat162*)&Ch[row * (long)ldc + col] =
                        __nv_bfloat162(h0, h1);
                    *(__nv_bfloat162*)&Cl[row * (long)ldc + col] = __nv_bfloat162(
                        __float2bfloat16(v0 - __bfloat162float(h0)),
                        __float2bfloat16(v1 - __bfloat162float(h1)));
                } else {
                    *(float2*)&C[row * (long)ldc + col] = make_float2(v0, v1);
                }
            }
        }
}

// =============================================================================
// step_mma (unchanged, proven): one GRU timestep via HMMA.
// grid (16 j-blocks, 8 k-splits) = 128 CTAs; device barrier; fused gates.
// =============================================================================
#define BSM_H    0
#define BSM_L    33792
#define ASM_BASE 67584
#define A_STAGE  20480
#define SM_DYN   (ASM_BASE + 2 * A_STAGE)   // 108544

__global__ __launch_bounds__(256, 1) void step_mma(
    const bf16* __restrict__ whh_hi,
    const bf16* __restrict__ whh_lo,
    const bf16* __restrict__ hh_in,
    const bf16* __restrict__ hl_in,
    const float* __restrict__ gx_t,
    const float* __restrict__ bhh,
    const float* __restrict__ h_prev,
    float* __restrict__ ghp,
    float* __restrict__ h_out,
    bf16* __restrict__ hh_out,
    bf16* __restrict__ hl_out,
    unsigned int* __restrict__ counter)
{
    extern __shared__ __align__(16) char smem[];
    const uint32_t sb = smem_u32(smem);
    const int tid = threadIdx.x;
    const int w = tid >> 5, l = tid & 31;
    const int j0 = blockIdx.x * 128;
    const int ks = blockIdx.y;
    const int k0 = ks * 256;
    const int wm = w >> 1, wn = w & 1;

#pragma unroll
    for (int i = 0; i < 8; i++) {
        int o = i * 256 + tid;
        int row = o >> 5, c = o & 31;
        cp16(sb + BSM_H + row * 528 + c * 16, hh_in + (size_t)row * CH_ + k0 + c * 8);
        cp16(sb + BSM_L + row * 528 + c * 16, hl_in + (size_t)row * CH_ + k0 + c * 8);
    }

    auto load_a = [&](int slot, int s) {
        const int gate = s >> 3, kt = s & 7;
        const uint32_t dst = sb + ASM_BASE + slot * A_STAGE;
#pragma unroll
        for (int i = 0; i < 2; i++) {
            int o = i * 256 + tid;
            int row = o >> 2, c = o & 3;
            size_t off = (size_t)(gate * CH_ + j0 + row) * CH_ + k0 + kt * 32 + c * 8;
            cp16(dst + row * 80 + c * 16, whh_hi + off);
            cp16(dst + 10240 + row * 80 + c * 16, whh_lo + off);
        }
        asm volatile("cp.async.commit_group;" ::: "memory");
    };
    load_a(0, 0);
    load_a(1, 1);

    const uint32_t aoff = (uint32_t)((l & 15) * 80 + (l >> 4) * 16);
    const uint32_t boff = (uint32_t)((wn * 32 + (l & 7) + ((l >> 4) & 1) * 8) * 528
                                     + ((l >> 3) & 1) * 16);

    float acc[2][4][4];
#pragma unroll
    for (int a = 0; a < 2; a++)
#pragma unroll
        for (int b = 0; b < 4; b++)
#pragma unroll
            for (int c = 0; c < 4; c++) acc[a][b][c] = 0.0f;

    for (int s = 0; s < 24; s++) {
        const int slot = s & 1;
        const int kt = s & 7;
        if (s < 23) asm volatile("cp.async.wait_group 1;" ::: "memory");
        else        asm volatile("cp.async.wait_group 0;" ::: "memory");
        __syncthreads();

        const uint32_t aH = sb + ASM_BASE + slot * A_STAGE + (uint32_t)(wm * 2560) + aoff;
        const uint32_t bHb = sb + BSM_H + boff + kt * 64;
        const uint32_t bLb = sb + BSM_L + boff + kt * 64;

#pragma unroll
        for (int k16 = 0; k16 < 2; k16++) {
            uint32_t ah[2][4], al[2][4], bh[2][4], bl[2][4];
#pragma unroll
            for (int mf = 0; mf < 2; mf++) {
                ldm4(aH + mf * 1280 + k16 * 32, ah[mf]);
                ldm4(aH + 10240 + mf * 1280 + k16 * 32, al[mf]);
            }
#pragma unroll
            for (int nf = 0; nf < 2; nf++) {
                ldm4(bHb + nf * 8448 + k16 * 32, bh[nf]);
                ldm4(bLb + nf * 8448 + k16 * 32, bl[nf]);
            }
#pragma unroll
            for (int mf = 0; mf < 2; mf++)
#pragma unroll
                for (int nf = 0; nf < 4; nf++) {
                    const uint32_t* bp = bh[nf >> 1];
                    const uint32_t* lp = bl[nf >> 1];
                    uint32_t b0 = bp[(nf & 1) * 2], b1 = bp[(nf & 1) * 2 + 1];
                    uint32_t c0 = lp[(nf & 1) * 2], c1 = lp[(nf & 1) * 2 + 1];
                    mma16816(acc[mf][nf], ah[mf], b0, b1);
                    mma16816(acc[mf][nf], ah[mf], c0, c1);
                    mma16816(acc[mf][nf], al[mf], b0, b1);
                }
        }
        __syncthreads();
        if (s + 2 < 24) load_a(slot, s + 2);

        if (kt == 7) {
            const int gate = s >> 3;
            float* base = ghp + (size_t)ks * B_ * G_;
            const int jb = gate * CH_ + j0 + wm * 32 + (l >> 2);
            const int bb = wn * 32 + (l & 3) * 2;
#pragma unroll
            for (int mf = 0; mf < 2; mf++)
#pragma unroll
                for (int nf = 0; nf < 4; nf++) {
                    const int j = jb + mf * 16;
                    const int b = bb + nf * 8;
                    base[(size_t)b * G_ + j]           = acc[mf][nf][0];
                    base[(size_t)(b + 1) * G_ + j]     = acc[mf][nf][1];
                    base[(size_t)b * G_ + j + 8]       = acc[mf][nf][2];
                    base[(size_t)(b + 1) * G_ + j + 8] = acc[mf][nf][3];
                    acc[mf][nf][0] = acc[mf][nf][1] = 0.0f;
                    acc[mf][nf][2] = acc[mf][nf][3] = 0.0f;
                }
        }
    }

    __threadfence();
    __syncthreads();
    if (tid == 0) {
        atomicAdd(counter, 1u);
        while (atomicAdd(counter, 0u) < (unsigned)NCTA_STEP) { }
    }
    __syncthreads();

    const int cta = blockIdx.y * 16 + blockIdx.x;
    const int idx4 = cta * 256 + tid;
    {
        const int b  = idx4 >> 9;
        const int j4 = idx4 & 511;
        const long go = (long)b * G_ + j4 * 4;

        float4 xr = *(const float4*)(gx_t + go);
        float4 xz = *(const float4*)(gx_t + go + CH_);
        float4 xn = *(const float4*)(gx_t + go + 2*CH_);

        float4 hr = *(const float4*)(ghp + go);
        float4 hz = *(const float4*)(ghp + go + CH_);
        float4 hn = *(const float4*)(ghp + go + 2*CH_);
#pragma unroll
        for (int s = 1; s < KSPLIT; s++) {
            const float* p = ghp + (size_t)s * B_ * G_ + go;
            float4 a = *(const float4*)(p);
            float4 c = *(const float4*)(p + CH_);
            float4 d = *(const float4*)(p + 2*CH_);
            hr.x += a.x; hr.y += a.y; hr.z += a.z; hr.w += a.w;
            hz.x += c.x; hz.y += c.y; hz.z += c.z; hz.w += c.w;
            hn.x += d.x; hn.y += d.y; hn.z += d.z; hn.w += d.w;
        }
        float4 br = *(const float4*)(bhh + j4*4);
        float4 bz = *(const float4*)(bhh + CH_ + j4*4);
        float4 bn = *(const float4*)(bhh + 2*CH_ + j4*4);
        float4 hp = *(const float4*)(h_prev + (long)b * CH_ + j4*4);

        float xrv[4] = {xr.x, xr.y, xr.z, xr.w};
        float xzv[4] = {xz.x, xz.y, xz.z, xz.w};
        float xnv[4] = {xn.x, xn.y, xn.z, xn.w};
        float hrv[4] = {hr.x + br.x, hr.y + br.y, hr.z + br.z, hr.w + br.w};
        float hzv[4] = {hz.x + bz.x, hz.y + bz.y, hz.z + bz.z, hz.w + bz.w};
        float hnv[4] = {hn.x + bn.x, hn.y + bn.y, hn.z + bn.z, hn.w + bn.w};
        float hpv[4] = {hp.x, hp.y, hp.z, hp.w};
        float ov[4];
#pragma unroll
        for (int i = 0; i < 4; i++) {
            float r = 1.0f / (1.0f + expf(-(xrv[i] + hrv[i])));
            float z = 1.0f / (1.0f + expf(-(xzv[i] + hzv[i])));
            float n = tanhf(xnv[i] + r * hnv[i]);
            ov[i] = (1.0f - z) * n + z * hpv[i];
        }
        const long ho = (long)b * CH_ + j4 * 4;
        *(float4*)(h_out + ho) = make_float4(ov[0], ov[1], ov[2], ov[3]);
#pragma unroll
        for (int i = 0; i < 4; i++) {
            bf16 hi = __float2bfloat16(ov[i]);
            hh_out[ho + i] = hi;
            hl_out[ho + i] = __float2bfloat16(ov[i] - __bfloat162float(hi));
        }
    }
}

// =============================================================================
extern "C" void kernel_launch(void* const* d_in, const int* in_sizes, int n_in,
                              void* d_out, int out_size)
{
    const float* x    = (const float*)d_in[0];
    const float* We   = (const float*)d_in[1];
    const float* be   = (const float*)d_in[2];
    const float* Wih  = (const float*)d_in[3];
    const float* bih  = (const float*)d_in[4];
    const float* Whh  = (const float*)d_in[5];
    const float* bhh  = (const float*)d_in[6];
    const float* Wmu  = (const float*)d_in[7];
    const float* bmu  = (const float*)d_in[8];
    const float* Wsig = (const float*)d_in[9];
    const float* bsig = (const float*)d_in[10];

    float* out        = (float*)d_out;
    float* out_mu     = out;
    float* out_sig    = out + (size_t)MB_ * DOUT_;
    float* out_hidden = out + (size_t)2 * MB_ * DOUT_;

    float *p_gx, *p_ghp, *p_h0;
    bf16 *p_xh, *p_xl, *p_xeh, *p_xel, *p_weh, *p_wel, *p_wihh, *p_wihl;
    bf16 *p_whhh, *p_whhl, *p_wmuh, *p_wmul, *p_wsgh, *p_wsgl;
    bf16 *p_hhA, *p_hlA, *p_hh0, *p_hl0;
    unsigned int* p_cnt;
    cudaGetSymbolAddress((void**)&p_gx, g_gx);
    cudaGetSymbolAddress((void**)&p_ghp, g_ghp);
    cudaGetSymbolAddress((void**)&p_h0, g_h0);
    cudaGetSymbolAddress((void**)&p_xh, g_xh);
    cudaGetSymbolAddress((void**)&p_xl, g_xl);
    cudaGetSymbolAddress((void**)&p_xeh, g_xeh);
    cudaGetSymbolAddress((void**)&p_xel, g_xel);
    cudaGetSymbolAddress((void**)&p_weh, g_weh);
    cudaGetSymbolAddress((void**)&p_wel, g_wel);
    cudaGetSymbolAddress((void**)&p_wihh, g_wihh);
    cudaGetSymbolAddress((void**)&p_wihl, g_wihl);
    cudaGetSymbolAddress((void**)&p_whhh, g_whh_hi);
    cudaGetSymbolAddress((void**)&p_whhl, g_whh_lo);
    cudaGetSymbolAddress((void**)&p_wmuh, g_wmuh);
    cudaGetSymbolAddress((void**)&p_wmul, g_wmul);
    cudaGetSymbolAddress((void**)&p_wsgh, g_wsgh);
    cudaGetSymbolAddress((void**)&p_wsgl, g_wsgl);
    cudaGetSymbolAddress((void**)&p_hhA, g_hhA);
    cudaGetSymbolAddress((void**)&p_hlA, g_hlA);
    cudaGetSymbolAddress((void**)&p_hh0, g_hh0);
    cudaGetSymbolAddress((void**)&p_hl0, g_hl0);
    cudaGetSymbolAddress((void**)&p_cnt, g_cnt);
    const size_t HB = (size_t)B_ * CH_;

    cudaFuncSetAttribute(step_mma, cudaFuncAttributeMaxDynamicSharedMemorySize, SM_DYN);
    cudaFuncSetAttribute(gemm_tc<0,0>, cudaFuncAttributeMaxDynamicSharedMemorySize, GT_SMEM);
    cudaFuncSetAttribute(gemm_tc<1,0>, cudaFuncAttributeMaxDynamicSharedMemorySize, GT_SMEM);
    cudaFuncSetAttribute(gemm_tc<2,0>, cudaFuncAttributeMaxDynamicSharedMemorySize, GT_SMEM);
    cudaFuncSetAttribute(gemm_tc<1,1>, cudaFuncAttributeMaxDynamicSharedMemorySize, GT_SMEM);

    dim3 blk(256);
    init_kernel<<<512, blk>>>();
    split_f2b<<<(int)((size_t)MB_ * DIN_ / 1024), blk>>>(x, p_xh, p_xl);
    split_f2b<<<(int)((size_t)H_ * DIN_ / 1024), blk>>>(We, p_weh, p_wel);
    split_f2b<<<(int)((size_t)G_ * H_ / 1024), blk>>>(Wih, p_wihh, p_wihl);
    split_f2b<<<(int)((size_t)G_ * CH_ / 1024), blk>>>(Whh, p_whhh, p_whhl);
    split_f2b<<<(int)((size_t)DOUT_ * H_ / 1024), blk>>>(Wmu, p_wmuh, p_wmul);
    split_f2b<<<(int)((size_t)DOUT_ * H_ / 1024), blk>>>(Wsig, p_wsgh, p_wsgl);

    // enc: xe = elu(x @ We^T + be) -> bf16 hi/lo, K=512  (ldc = H_ !!)
    gemm_tc<1,1><<<dim3(H_/128, MB_/128), blk, GT_SMEM>>>(
        p_xh, p_xl, DIN_, p_weh, p_wel, DIN_, be,
        nullptr, H_, p_xeh, p_xel, DIN_);
    // gx = xe @ Wih^T + bih (fp32), K=1024
    gemm_tc<0,0><<<dim3(G_/128, MB_/128), blk, GT_SMEM>>>(
        p_xeh, p_xel, H_, p_wihh, p_wihl, H_, bih,
        p_gx, G_, nullptr, nullptr, H_);

    // recurrence
    for (int t = 0; t < T_; t++) {
        const float* hp = (t == 0) ? p_h0
                                   : out_hidden + (size_t)(t - 1) * HB;
        const bf16* hhi = (t == 0) ? p_hh0 : p_hhA + (size_t)(t - 1) * HB;
        const bf16* hli = (t == 0) ? p_hl0 : p_hlA + (size_t)(t - 1) * HB;
        step_mma<<<dim3(16, KSPLIT), blk, SM_DYN>>>(
            p_whhh, p_whhl, hhi, hli,
            p_gx + (size_t)t * B_ * G_, bhh, hp, p_ghp,
            out_hidden + (size_t)t * HB,
            p_hhA + (size_t)t * HB, p_hlA + (size_t)t * HB, p_cnt + t);
    }

    // heads (K=1024); mu uses hidden cols [0,1024), sig uses [1024,2048)
    gemm_tc<1,0><<<dim3(DOUT_/128, MB_/128), blk, GT_SMEM>>>(
        p_hhA, p_hlA, CH_, p_wmuh, p_wmul, H_, bmu,
        out_mu, DOUT_, nullptr, nullptr, H_);
    gemm_tc<2,0><<<dim3(DOUT_/128, MB_/128), blk, GT_SMEM>>>(
        p_hhA + H_, p_hlA + H_, CH_, p_wsgh, p_wsgl, H_, bsig,
        out_sig, DOUT_, nullptr, nullptr, H_);
}

// round 9
// speedup vs baseline: 4.4360x; 1.0425x over previous
#include <cuda_runtime.h>
#include <cuda_bf16.h>
#include <cstdint>
#include <cstddef>

#define T_    256
#define B_    64
#define DIN_  512
#define H_    1024
#define CH_   2048
#define G_    6144
#define DOUT_ 512
#define MB_   (T_*B_)
#define KSPLIT 8
#define NCTA_STEP 128
#define HB_   ((size_t)B_ * CH_)

typedef __nv_bfloat16 bf16;

// ---------------- scratch (device globals) ----------------------------------
__device__ float g_gx[(size_t)MB_ * G_];
__device__ float g_ghp[(size_t)KSPLIT * B_ * G_];
__device__ bf16 g_xh[(size_t)MB_ * DIN_],  g_xl[(size_t)MB_ * DIN_];
__device__ bf16 g_xeh[(size_t)MB_ * H_],   g_xel[(size_t)MB_ * H_];
__device__ bf16 g_weh[(size_t)H_ * DIN_],  g_wel[(size_t)H_ * DIN_];
__device__ bf16 g_wihh[(size_t)G_ * H_],   g_wihl[(size_t)G_ * H_];
__device__ bf16 g_whh_hi[(size_t)G_ * CH_], g_whh_lo[(size_t)G_ * CH_];
__device__ bf16 g_wmuh[(size_t)DOUT_ * H_], g_wmul[(size_t)DOUT_ * H_];
__device__ bf16 g_wsgh[(size_t)DOUT_ * H_], g_wsgl[(size_t)DOUT_ * H_];
__device__ bf16 g_hhA[(size_t)MB_ * CH_],  g_hlA[(size_t)MB_ * CH_];
__device__ bf16 g_hh0[HB_],                g_hl0[HB_];
__device__ unsigned int g_cnt[2 * T_];

__device__ __forceinline__ float act_elu(float v) {
    return v > 0.0f ? v : expm1f(v);
}
__device__ __forceinline__ float act_softplus01(float v) {
    return fmaxf(v, 0.0f) + log1pf(expf(-fabsf(v))) + 0.1f;
}

// ---------------- sm_80-era primitives ---------------------------------------
__device__ __forceinline__ uint32_t smem_u32(const void* p) {
    uint32_t a;
    asm("{ .reg .u64 t; cvta.to.shared.u64 t, %1; cvt.u32.u64 %0, t; }"
        : "=r"(a) : "l"(p));
    return a;
}
__device__ __forceinline__ void cp16(uint32_t dst, const void* src) {
    asm volatile("cp.async.cg.shared.global [%0], [%1], 16;"
                 :: "r"(dst), "l"(src) : "memory");
}
__device__ __forceinline__ void ldm4(uint32_t addr, uint32_t r[4]) {
    asm volatile("ldmatrix.sync.aligned.m8n8.x4.shared.b16 {%0,%1,%2,%3}, [%4];"
                 : "=r"(r[0]), "=r"(r[1]), "=r"(r[2]), "=r"(r[3]) : "r"(addr));
}
__device__ __forceinline__ void mma16816(float d[4], const uint32_t a[4],
                                         uint32_t b0, uint32_t b1) {
    asm volatile(
        "mma.sync.aligned.m16n8k16.row.col.f32.bf16.bf16.f32 "
        "{%0,%1,%2,%3}, {%4,%5,%6,%7}, {%8,%9}, {%0,%1,%2,%3};"
        : "+f"(d[0]), "+f"(d[1]), "+f"(d[2]), "+f"(d[3])
        : "r"(a[0]), "r"(a[1]), "r"(a[2]), "r"(a[3]), "r"(b0), "r"(b1));
}
#define CPW(n) asm volatile("cp.async.wait_group " #n ";" ::: "memory")
#define CPC()  asm volatile("cp.async.commit_group;" ::: "memory")

// =============================================================================
__global__ void init_kernel() {
    int idx = blockIdx.x * 256 + threadIdx.x;          // grid 512 -> 131072
    g_hh0[idx] = __float2bfloat16(0.0f);
    g_hl0[idx] = __float2bfloat16(0.0f);
    if (idx < 2 * T_) g_cnt[idx] = 0u;
}

// split fp32 -> bf16 hi + lo (n divisible by 1024; grid = n/1024)
__global__ void split_f2b(const float* __restrict__ src,
                          bf16* __restrict__ hi, bf16* __restrict__ lo) {
    size_t i = ((size_t)blockIdx.x * 256 + threadIdx.x) * 4;
    float4 w = *(const float4*)(src + i);
    float f[4] = {w.x, w.y, w.z, w.w};
#pragma unroll
    for (int k = 0; k < 4; k++) {
        bf16 h = __float2bfloat16(f[k]);
        hi[i + k] = h;
        lo[i + k] = __float2bfloat16(f[k] - __bfloat162float(h));
    }
}

// =============================================================================
// gemm_tc (proven round 8): C = act(A @ W^T + bias) via bf16 HMMA 3-term split.
// =============================================================================
#define GT_TILE  10240        // 128 rows x 80 B
#define GT_STAGE (4*GT_TILE)
#define GT_SMEM  (2*GT_STAGE)

template <int ACT, int SPLIT>
__global__ __launch_bounds__(256) void gemm_tc(
    const bf16* __restrict__ Ah, const bf16* __restrict__ Al, int lda,
    const bf16* __restrict__ Wh, const bf16* __restrict__ Wl, int ldw,
    const float* __restrict__ bias,
    float* __restrict__ C, int ldc,
    bf16* __restrict__ Ch, bf16* __restrict__ Cl,
    int K)
{
    extern __shared__ __align__(16) char smem[];
    const uint32_t sb = smem_u32(smem);
    const int tid = threadIdx.x;
    const int w = tid >> 5, l = tid & 31;
    const int wm = w >> 1, wn = w & 1;
    const long m0 = (long)blockIdx.y * 128;
    const long n0 = (long)blockIdx.x * 128;

    auto load_stage = [&](int slot, int kt) {
        const uint32_t dst = sb + slot * GT_STAGE;
        const int k0 = kt * 32;
#pragma unroll
        for (int i = 0; i < 2; i++) {
            int o = i * 256 + tid;
            int row = o >> 2, c = o & 3;
            size_t ao = (m0 + row) * (size_t)lda + k0 + c * 8;
            size_t wo = (n0 + row) * (size_t)ldw + k0 + c * 8;
            uint32_t d = dst + row * 80 + c * 16;
            cp16(d,               Ah + ao);
            cp16(d + GT_TILE,     Al + ao);
            cp16(d + 2*GT_TILE,   Wh + wo);
            cp16(d + 3*GT_TILE,   Wl + wo);
        }
        CPC();
    };

    const int nst = K >> 5;
    load_stage(0, 0);
    load_stage(1, 1);

    const uint32_t aoff = (uint32_t)((l & 15) * 80 + (l >> 4) * 16);
    const uint32_t woff = (uint32_t)(((l & 7) + ((l >> 4) & 1) * 8) * 80
                                     + ((l >> 3) & 1) * 16);

    float acc[2][8][4];
#pragma unroll
    for (int a = 0; a < 2; a++)
#pragma unroll
        for (int b = 0; b < 8; b++)
#pragma unroll
            for (int c = 0; c < 4; c++) acc[a][b][c] = 0.0f;

    for (int s = 0; s < nst; s++) {
        const int slot = s & 1;
        if (s + 1 < nst) CPW(1);
        else             CPW(0);
        __syncthreads();

        const uint32_t stg = sb + slot * GT_STAGE;
        const uint32_t aH = stg + wm * 2560 + aoff;
        const uint32_t wH = stg + 2*GT_TILE + wn * 5120 + woff;

#pragma unroll
        for (int k16 = 0; k16 < 2; k16++) {
            uint32_t ah[2][4], al[2][4], wh[4][4], wl[4][4];
#pragma unroll
            for (int mf = 0; mf < 2; mf++) {
                ldm4(aH + mf * 1280 + k16 * 32, ah[mf]);
                ldm4(aH + GT_TILE + mf * 1280 + k16 * 32, al[mf]);
            }
#pragma unroll
            for (int g = 0; g < 4; g++) {
                ldm4(wH + g * 1280 + k16 * 32, wh[g]);
                ldm4(wH + GT_TILE + g * 1280 + k16 * 32, wl[g]);
            }
#pragma unroll
            for (int mf = 0; mf < 2; mf++)
#pragma unroll
                for (int nf = 0; nf < 8; nf++) {
                    const uint32_t* bp = wh[nf >> 1];
                    const uint32_t* lp = wl[nf >> 1];
                    uint32_t b0 = bp[(nf & 1) * 2], b1 = bp[(nf & 1) * 2 + 1];
                    uint32_t c0 = lp[(nf & 1) * 2], c1 = lp[(nf & 1) * 2 + 1];
                    mma16816(acc[mf][nf], ah[mf], b0, b1);
                    mma16816(acc[mf][nf], ah[mf], c0, c1);
                    mma16816(acc[mf][nf], al[mf], b0, b1);
                }
        }
        __syncthreads();
        if (s + 2 < nst) load_stage(slot, s + 2);
    }

    const int r0 = wm * 32 + (l >> 2);
    const int c0 = wn * 64 + (l & 3) * 2;
#pragma unroll
    for (int mf = 0; mf < 2; mf++)
#pragma unroll
        for (int nf = 0; nf < 8; nf++) {
            const long col = n0 + c0 + nf * 8;
            const float b0 = bias[col], b1 = bias[col + 1];
#pragma unroll
            for (int rr = 0; rr < 2; rr++) {
                const long row = m0 + r0 + mf * 16 + rr * 8;
                float v0 = acc[mf][nf][rr * 2]     + b0;
                float v1 = acc[mf][nf][rr * 2 + 1] + b1;
                if (ACT == 1) { v0 = act_elu(v0); v1 = act_elu(v1); }
                else if (ACT == 2) { v0 = act_softplus01(v0); v1 = act_softplus01(v1); }
                if (SPLIT) {
                    bf16 h0 = __float2bfloat16(v0);
                    bf16 h1 = __float2bfloat16(v1);
                    *(__nv_bfloat162*)&Ch[row * (long)ldc + col] =
                        __nv_bfloat162(h0, h1);
                    *(__nv_bfloat162*)&Cl[row * (long)ldc + col] = __nv_bfloat162(
                        __float2bfloat16(v0 - __bfloat162float(h0)),
                        __float2bfloat16(v1 - __bfloat162float(h1)));
                } else {
                    *(float2*)&C[row * (long)ldc + col] = make_float2(v0, v1);
                }
            }
        }
}

// =============================================================================
// step_persist: ALL 256 GRU timesteps in one persistent kernel.
// grid (16 j-blocks, 8 k-splits) = 128 CTAs (all resident).
// Per step: phase 1 (split-K HMMA partials, 4-deep cp.async pipeline) ->
// barrier -> phase 2 (reduce + gates, h in registers) -> barrier -> next B load.
// =============================================================================
#define BSM_H    0
#define BSM_L    33792
#define ASM_BASE 67584
#define A_STAGE  20480
#define SM_P     (ASM_BASE + 4 * A_STAGE)   // 149504

__global__ __launch_bounds__(256, 1) void step_persist(
    const bf16* __restrict__ whh_hi,
    const bf16* __restrict__ whh_lo,
    const bf16* __restrict__ hh0,
    const bf16* __restrict__ hl0,
    const float* __restrict__ gx,       // [T][64][6144]
    const float* __restrict__ bhh,
    float* __restrict__ ghp,            // [KSPLIT][64][6144]
    float* __restrict__ hidden,         // [T][64][2048]
    bf16* __restrict__ hhA,             // [T][64][2048]
    bf16* __restrict__ hlA,
    unsigned int* __restrict__ cnt)     // [2*T]
{
    extern __shared__ __align__(16) char smem[];
    const uint32_t sb = smem_u32(smem);
    const int tid = threadIdx.x;
    const int w = tid >> 5, l = tid & 31;
    const int j0 = blockIdx.x * 128;
    const int ks = blockIdx.y;
    const int k0 = ks * 256;
    const int wm = w >> 1, wn = w & 1;
    const int cta = blockIdx.y * 16 + blockIdx.x;

    auto load_a = [&](int s) {      // stage s -> slot s&3
        const int gate = s >> 3, kt = s & 7;
        const uint32_t dst = sb + ASM_BASE + (s & 3) * A_STAGE;
#pragma unroll
        for (int i = 0; i < 2; i++) {
            int o = i * 256 + tid;
            int row = o >> 2, c = o & 3;
            size_t off = (size_t)(gate * CH_ + j0 + row) * CH_ + k0 + kt * 32 + c * 8;
            cp16(dst + row * 80 + c * 16, whh_hi + off);
            cp16(dst + 10240 + row * 80 + c * 16, whh_lo + off);
        }
        CPC();
    };
    auto load_b = [&](const bf16* hh_in, const bf16* hl_in) {
#pragma unroll
        for (int i = 0; i < 8; i++) {
            int o = i * 256 + tid;
            int row = o >> 5, c = o & 31;
            cp16(sb + BSM_H + row * 528 + c * 16, hh_in + (size_t)row * CH_ + k0 + c * 8);
            cp16(sb + BSM_L + row * 528 + c * 16, hl_in + (size_t)row * CH_ + k0 + c * 8);
        }
        CPC();
    };

    // kernel-start prefetch: A0..A3 then B (group order A,A,A,A,B)
    load_a(0); load_a(1); load_a(2); load_a(3);
    load_b(hh0, hl0);

    const uint32_t aoff = (uint32_t)((l & 15) * 80 + (l >> 4) * 16);
    const uint32_t boff = (uint32_t)((wn * 32 + (l & 7) + ((l >> 4) & 1) * 8) * 528
                                     + ((l >> 3) & 1) * 16);

    // phase-2 per-thread constants (static element mapping across steps)
    const int idx4 = cta * 256 + tid;           // 0 .. 32767 = B_*CH_/4
    const int pb  = idx4 >> 9;
    const int pj4 = idx4 & 511;
    const float4 br4 = *(const float4*)(bhh + pj4 * 4);
    const float4 bz4 = *(const float4*)(bhh + CH_ + pj4 * 4);
    const float4 bn4 = *(const float4*)(bhh + 2 * CH_ + pj4 * 4);
    float4 hp = make_float4(0.f, 0.f, 0.f, 0.f);   // h state in registers

    float acc[2][4][4];
#pragma unroll
    for (int a = 0; a < 2; a++)
#pragma unroll
        for (int b = 0; b < 4; b++)
#pragma unroll
            for (int c = 0; c < 4; c++) acc[a][b][c] = 0.0f;

    for (int t = 0; t < T_; t++) {
        // ---------------- phase 1: split-K HMMA ----------------
        for (int g = 0; g < 3; g++) {
#pragma unroll
            for (int kt = 0; kt < 8; kt++) {
                // wait schedule (group order per step: A0..A3 first, B last)
                if      (kt == 0) { if (g == 0) CPW(0); else CPW(3); }
                else if (kt == 1) { if (g == 0) CPW(1); else CPW(3); }
                else if (kt == 2) { if (g == 0) CPW(2); else CPW(3); }
                else if (kt == 5) { if (g == 2) CPW(2); else CPW(3); }
                else if (kt == 6) { if (g == 2) CPW(1); else CPW(3); }
                else if (kt == 7) { if (g == 2) CPW(0); else CPW(3); }
                else              CPW(3);
                __syncthreads();

                const int s = g * 8 + kt;
                const uint32_t aH = sb + ASM_BASE + (s & 3) * A_STAGE
                                    + (uint32_t)(wm * 2560) + aoff;
                const uint32_t bHb = sb + BSM_H + boff + kt * 64;
                const uint32_t bLb = sb + BSM_L + boff + kt * 64;

                // hoist ALL fragment loads, then sync, then prefetch, then MMA
                uint32_t ah[2][2][4], al[2][2][4], bh[2][2][4], bl[2][2][4];
#pragma unroll
                for (int k16 = 0; k16 < 2; k16++) {
#pragma unroll
                    for (int mf = 0; mf < 2; mf++) {
                        ldm4(aH + mf * 1280 + k16 * 32, ah[k16][mf]);
                        ldm4(aH + 10240 + mf * 1280 + k16 * 32, al[k16][mf]);
                    }
#pragma unroll
                    for (int nf = 0; nf < 2; nf++) {
                        ldm4(bHb + nf * 8448 + k16 * 32, bh[k16][nf]);
                        ldm4(bLb + nf * 8448 + k16 * 32, bl[k16][nf]);
                    }
                }
                __syncthreads();
                if (!(g == 2 && kt >= 4)) load_a(s + 4);

#pragma unroll
                for (int k16 = 0; k16 < 2; k16++)
#pragma unroll
                    for (int mf = 0; mf < 2; mf++)
#pragma unroll
                        for (int nf = 0; nf < 4; nf++) {
                            const uint32_t* bp = bh[k16][nf >> 1];
                            const uint32_t* lp = bl[k16][nf >> 1];
                            uint32_t b0 = bp[(nf & 1) * 2], b1 = bp[(nf & 1) * 2 + 1];
                            uint32_t c0 = lp[(nf & 1) * 2], c1 = lp[(nf & 1) * 2 + 1];
                            mma16816(acc[mf][nf], ah[k16][mf], b0, b1);
                            mma16816(acc[mf][nf], ah[k16][mf], c0, c1);
                            mma16816(acc[mf][nf], al[k16][mf], b0, b1);
                        }

                if (kt == 7) {  // gate finished -> write partials, reset acc
                    float* base = ghp + (size_t)ks * B_ * G_;
                    const int jb = g * CH_ + j0 + wm * 32 + (l >> 2);
                    const int bb = wn * 32 + (l & 3) * 2;
#pragma unroll
                    for (int mf = 0; mf < 2; mf++)
#pragma unroll
                        for (int nf = 0; nf < 4; nf++) {
                            const int j = jb + mf * 16;
                            const int b = bb + nf * 8;
                            base[(size_t)b * G_ + j]           = acc[mf][nf][0];
                            base[(size_t)(b + 1) * G_ + j]     = acc[mf][nf][1];
                            base[(size_t)b * G_ + j + 8]       = acc[mf][nf][2];
                            base[(size_t)(b + 1) * G_ + j + 8] = acc[mf][nf][3];
                            acc[mf][nf][0] = acc[mf][nf][1] = 0.0f;
                            acc[mf][nf][2] = acc[mf][nf][3] = 0.0f;
                        }
                }
            }
        }

        // ---- barrier 1 (partials visible); prefetch next-step A during spin ----
        __threadfence();
        __syncthreads();
        if (t + 1 < T_) { load_a(0); load_a(1); load_a(2); load_a(3); }
        if (tid == 0) {
            atomicAdd(&cnt[2 * t], 1u);
            while (atomicAdd(&cnt[2 * t], 0u) < (unsigned)NCTA_STEP) { }
        }
        __syncthreads();

        // ---------------- phase 2: reduce + gates ----------------
        {
            const float* gx_t = gx + (size_t)t * B_ * G_;
            const long go = (long)pb * G_ + pj4 * 4;

            float4 xr = *(const float4*)(gx_t + go);
            float4 xz = *(const float4*)(gx_t + go + CH_);
            float4 xn = *(const float4*)(gx_t + go + 2*CH_);

            float4 hr = *(const float4*)(ghp + go);
            float4 hz = *(const float4*)(ghp + go + CH_);
            float4 hn = *(const float4*)(ghp + go + 2*CH_);
#pragma unroll
            for (int s = 1; s < KSPLIT; s++) {
                const float* p = ghp + (size_t)s * B_ * G_ + go;
                float4 a = *(const float4*)(p);
                float4 c = *(const float4*)(p + CH_);
                float4 d = *(const float4*)(p + 2*CH_);
                hr.x += a.x; hr.y += a.y; hr.z += a.z; hr.w += a.w;
                hz.x += c.x; hz.y += c.y; hz.z += c.z; hz.w += c.w;
                hn.x += d.x; hn.y += d.y; hn.z += d.z; hn.w += d.w;
            }
            float xrv[4] = {xr.x, xr.y, xr.z, xr.w};
            float xzv[4] = {xz.x, xz.y, xz.z, xz.w};
            float xnv[4] = {xn.x, xn.y, xn.z, xn.w};
            float hrv[4] = {hr.x + br4.x, hr.y + br4.y, hr.z + br4.z, hr.w + br4.w};
            float hzv[4] = {hz.x + bz4.x, hz.y + bz4.y, hz.z + bz4.z, hz.w + bz4.w};
            float hnv[4] = {hn.x + bn4.x, hn.y + bn4.y, hn.z + bn4.z, hn.w + bn4.w};
            float hpv[4] = {hp.x, hp.y, hp.z, hp.w};
            float ov[4];
#pragma unroll
            for (int i = 0; i < 4; i++) {
                float r = 1.0f / (1.0f + expf(-(xrv[i] + hrv[i])));
                float z = 1.0f / (1.0f + expf(-(xzv[i] + hzv[i])));
                float n = tanhf(xnv[i] + r * hnv[i]);
                ov[i] = (1.0f - z) * n + z * hpv[i];
            }
            hp = make_float4(ov[0], ov[1], ov[2], ov[3]);

            const long ho = (long)pb * CH_ + pj4 * 4;
            *(float4*)(hidden + (size_t)t * HB_ + ho) = hp;
            bf16* hhp = hhA + (size_t)t * HB_ + ho;
            bf16* hlp = hlA + (size_t)t * HB_ + ho;
#pragma unroll
            for (int i = 0; i < 4; i++) {
                bf16 hi = __float2bfloat16(ov[i]);
                hhp[i] = hi;
                hlp[i] = __float2bfloat16(ov[i] - __bfloat162float(hi));
            }
        }

        // ---- barrier 2 (h(t) visible) ----
        __threadfence();
        __syncthreads();
        if (tid == 0) {
            atomicAdd(&cnt[2 * t + 1], 1u);
            while (atomicAdd(&cnt[2 * t + 1], 0u) < (unsigned)NCTA_STEP) { }
        }
        __syncthreads();

        // load next-step B (h hi/lo just produced)
        if (t + 1 < T_)
            load_b(hhA + (size_t)t * HB_, hlA + (size_t)t * HB_);
    }
}

// =============================================================================
extern "C" void kernel_launch(void* const* d_in, const int* in_sizes, int n_in,
                              void* d_out, int out_size)
{
    const float* x    = (const float*)d_in[0];
    const float* We   = (const float*)d_in[1];
    const float* be   = (const float*)d_in[2];
    const float* Wih  = (const float*)d_in[3];
    const float* bih  = (const float*)d_in[4];
    const float* Whh  = (const float*)d_in[5];
    const float* bhh  = (const float*)d_in[6];
    const float* Wmu  = (const float*)d_in[7];
    const float* bmu  = (const float*)d_in[8];
    const float* Wsig = (const float*)d_in[9];
    const float* bsig = (const float*)d_in[10];

    float* out        = (float*)d_out;
    float* out_mu     = out;
    float* out_sig    = out + (size_t)MB_ * DOUT_;
    float* out_hidden = out + (size_t)2 * MB_ * DOUT_;

    float *p_gx, *p_ghp;
    bf16 *p_xh, *p_xl, *p_xeh, *p_xel, *p_weh, *p_wel, *p_wihh, *p_wihl;
    bf16 *p_whhh, *p_whhl, *p_wmuh, *p_wmul, *p_wsgh, *p_wsgl;
    bf16 *p_hhA, *p_hlA, *p_hh0, *p_hl0;
    unsigned int* p_cnt;
    cudaGetSymbolAddress((void**)&p_gx, g_gx);
    cudaGetSymbolAddress((void**)&p_ghp, g_ghp);
    cudaGetSymbolAddress((void**)&p_xh, g_xh);
    cudaGetSymbolAddress((void**)&p_xl, g_xl);
    cudaGetSymbolAddress((void**)&p_xeh, g_xeh);
    cudaGetSymbolAddress((void**)&p_xel, g_xel);
    cudaGetSymbolAddress((void**)&p_weh, g_weh);
    cudaGetSymbolAddress((void**)&p_wel, g_wel);
    cudaGetSymbolAddress((void**)&p_wihh, g_wihh);
    cudaGetSymbolAddress((void**)&p_wihl, g_wihl);
    cudaGetSymbolAddress((void**)&p_whhh, g_whh_hi);
    cudaGetSymbolAddress((void**)&p_whhl, g_whh_lo);
    cudaGetSymbolAddress((void**)&p_wmuh, g_wmuh);
    cudaGetSymbolAddress((void**)&p_wmul, g_wmul);
    cudaGetSymbolAddress((void**)&p_wsgh, g_wsgh);
    cudaGetSymbolAddress((void**)&p_wsgl, g_wsgl);
    cudaGetSymbolAddress((void**)&p_hhA, g_hhA);
    cudaGetSymbolAddress((void**)&p_hlA, g_hlA);
    cudaGetSymbolAddress((void**)&p_hh0, g_hh0);
    cudaGetSymbolAddress((void**)&p_hl0, g_hl0);
    cudaGetSymbolAddress((void**)&p_cnt, g_cnt);

    cudaFuncSetAttribute(step_persist, cudaFuncAttributeMaxDynamicSharedMemorySize, SM_P);
    cudaFuncSetAttribute(gemm_tc<0,0>, cudaFuncAttributeMaxDynamicSharedMemorySize, GT_SMEM);
    cudaFuncSetAttribute(gemm_tc<1,0>, cudaFuncAttributeMaxDynamicSharedMemorySize, GT_SMEM);
    cudaFuncSetAttribute(gemm_tc<2,0>, cudaFuncAttributeMaxDynamicSharedMemorySize, GT_SMEM);
    cudaFuncSetAttribute(gemm_tc<1,1>, cudaFuncAttributeMaxDynamicSharedMemorySize, GT_SMEM);

    dim3 blk(256);
    init_kernel<<<512, blk>>>();
    split_f2b<<<(int)((size_t)MB_ * DIN_ / 1024), blk>>>(x, p_xh, p_xl);
    split_f2b<<<(int)((size_t)H_ * DIN_ / 1024), blk>>>(We, p_weh, p_wel);
    split_f2b<<<(int)((size_t)G_ * H_ / 1024), blk>>>(Wih, p_wihh, p_wihl);
    split_f2b<<<(int)((size_t)G_ * CH_ / 1024), blk>>>(Whh, p_whhh, p_whhl);
    split_f2b<<<(int)((size_t)DOUT_ * H_ / 1024), blk>>>(Wmu, p_wmuh, p_wmul);
    split_f2b<<<(int)((size_t)DOUT_ * H_ / 1024), blk>>>(Wsig, p_wsgh, p_wsgl);

    // enc: xe = elu(x @ We^T + be) -> bf16 hi/lo, K=512 (ldc = H_)
    gemm_tc<1,1><<<dim3(H_/128, MB_/128), blk, GT_SMEM>>>(
        p_xh, p_xl, DIN_, p_weh, p_wel, DIN_, be,
        nullptr, H_, p_xeh, p_xel, DIN_);
    // gx = xe @ Wih^T + bih (fp32), K=1024
    gemm_tc<0,0><<<dim3(G_/128, MB_/128), blk, GT_SMEM>>>(
        p_xeh, p_xel, H_, p_wihh, p_wihl, H_, bih,
        p_gx, G_, nullptr, nullptr, H_);

    // recurrence: ONE persistent kernel for all 256 steps
    step_persist<<<dim3(16, KSPLIT), blk, SM_P>>>(
        p_whhh, p_whhl, p_hh0, p_hl0, p_gx, bhh, p_ghp,
        out_hidden, p_hhA, p_hlA, p_cnt);

    // heads (K=1024)
    gemm_tc<1,0><<<dim3(DOUT_/128, MB_/128), blk, GT_SMEM>>>(
        p_hhA, p_hlA, CH_, p_wmuh, p_wmul, H_, bmu,
        out_mu, DOUT_, nullptr, nullptr, H_);
    gemm_tc<2,0><<<dim3(DOUT_/128, MB_/128), blk, GT_SMEM>>>(
        p_hhA + H_, p_hlA + H_, CH_, p_wsgh, p_wsgl, H_, bsig,
        out_sig, DOUT_, nullptr, nullptr, H_);
}

// round 10
// speedup vs baseline: 4.7171x; 1.0634x over previous
#include <cuda_runtime.h>
#include <cuda_bf16.h>
#include <cstdint>
#include <cstddef>

#define T_    256
#define B_    64
#define DIN_  512
#define H_    1024
#define CH_   2048
#define G_    6144
#define DOUT_ 512
#define MB_   (T_*B_)
#define KSPLIT 3
#define NCTA_STEP 144
#define HB_   ((size_t)B_ * CH_)

typedef __nv_bfloat16 bf16;

// ---------------- scratch (device globals) ----------------------------------
__device__ float g_gx[(size_t)MB_ * G_];
__device__ float g_ghp[(size_t)KSPLIT * B_ * G_];
__device__ bf16 g_xh[(size_t)MB_ * DIN_],  g_xl[(size_t)MB_ * DIN_];
__device__ bf16 g_xeh[(size_t)MB_ * H_],   g_xel[(size_t)MB_ * H_];
__device__ bf16 g_weh[(size_t)H_ * DIN_],  g_wel[(size_t)H_ * DIN_];
__device__ bf16 g_wihh[(size_t)G_ * H_],   g_wihl[(size_t)G_ * H_];
__device__ bf16 g_whh_hi[(size_t)G_ * CH_], g_whh_lo[(size_t)G_ * CH_];
__device__ bf16 g_wmuh[(size_t)DOUT_ * H_], g_wmul[(size_t)DOUT_ * H_];
__device__ bf16 g_wsgh[(size_t)DOUT_ * H_], g_wsgl[(size_t)DOUT_ * H_];
__device__ bf16 g_hhA[(size_t)MB_ * CH_],  g_hlA[(size_t)MB_ * CH_];
__device__ bf16 g_hh0[HB_],                g_hl0[HB_];
__device__ unsigned int g_cnt[2 * T_];

__device__ __forceinline__ float act_elu(float v) {
    return v > 0.0f ? v : expm1f(v);
}
__device__ __forceinline__ float act_softplus01(float v) {
    return fmaxf(v, 0.0f) + log1pf(expf(-fabsf(v))) + 0.1f;
}

// ---------------- sm_80-era primitives ---------------------------------------
__device__ __forceinline__ uint32_t smem_u32(const void* p) {
    uint32_t a;
    asm("{ .reg .u64 t; cvta.to.shared.u64 t, %1; cvt.u32.u64 %0, t; }"
        : "=r"(a) : "l"(p));
    return a;
}
__device__ __forceinline__ void cp16(uint32_t dst, const void* src) {
    asm volatile("cp.async.cg.shared.global [%0], [%1], 16;"
                 :: "r"(dst), "l"(src) : "memory");
}
__device__ __forceinline__ void ldm4(uint32_t addr, uint32_t r[4]) {
    asm volatile("ldmatrix.sync.aligned.m8n8.x4.shared.b16 {%0,%1,%2,%3}, [%4];"
                 : "=r"(r[0]), "=r"(r[1]), "=r"(r[2]), "=r"(r[3]) : "r"(addr));
}
__device__ __forceinline__ void mma16816(float d[4], const uint32_t a[4],
                                         uint32_t b0, uint32_t b1) {
    asm volatile(
        "mma.sync.aligned.m16n8k16.row.col.f32.bf16.bf16.f32 "
        "{%0,%1,%2,%3}, {%4,%5,%6,%7}, {%8,%9}, {%0,%1,%2,%3};"
        : "+f"(d[0]), "+f"(d[1]), "+f"(d[2]), "+f"(d[3])
        : "r"(a[0]), "r"(a[1]), "r"(a[2]), "r"(a[3]), "r"(b0), "r"(b1));
}
#define CPW(n) asm volatile("cp.async.wait_group " #n ";" ::: "memory")
#define CPC()  asm volatile("cp.async.commit_group;" ::: "memory")

// =============================================================================
__global__ void init_kernel() {
    int idx = blockIdx.x * 256 + threadIdx.x;          // grid 512 -> 131072
    g_hh0[idx] = __float2bfloat16(0.0f);
    g_hl0[idx] = __float2bfloat16(0.0f);
    if (idx < 2 * T_) g_cnt[idx] = 0u;
}

// split fp32 -> bf16 hi + lo (n divisible by 1024; grid = n/1024)
__global__ void split_f2b(const float* __restrict__ src,
                          bf16* __restrict__ hi, bf16* __restrict__ lo) {
    size_t i = ((size_t)blockIdx.x * 256 + threadIdx.x) * 4;
    float4 w = *(const float4*)(src + i);
    float f[4] = {w.x, w.y, w.z, w.w};
#pragma unroll
    for (int k = 0; k < 4; k++) {
        bf16 h = __float2bfloat16(f[k]);
        hi[i + k] = h;
        lo[i + k] = __float2bfloat16(f[k] - __bfloat162float(h));
    }
}

// =============================================================================
// gemm_tc (proven round 8): C = act(A @ W^T + bias) via bf16 HMMA 3-term split.
// =============================================================================
#define GT_TILE  10240        // 128 rows x 80 B
#define GT_STAGE (4*GT_TILE)
#define GT_SMEM  (2*GT_STAGE)

template <int ACT, int SPLIT>
__global__ __launch_bounds__(256) void gemm_tc(
    const bf16* __restrict__ Ah, const bf16* __restrict__ Al, int lda,
    const bf16* __restrict__ Wh, const bf16* __restrict__ Wl, int ldw,
    const float* __restrict__ bias,
    float* __restrict__ C, int ldc,
    bf16* __restrict__ Ch, bf16* __restrict__ Cl,
    int K)
{
    extern __shared__ __align__(16) char smem[];
    const uint32_t sb = smem_u32(smem);
    const int tid = threadIdx.x;
    const int w = tid >> 5, l = tid & 31;
    const int wm = w >> 1, wn = w & 1;
    const long m0 = (long)blockIdx.y * 128;
    const long n0 = (long)blockIdx.x * 128;

    auto load_stage = [&](int slot, int kt) {
        const uint32_t dst = sb + slot * GT_STAGE;
        const int k0 = kt * 32;
#pragma unroll
        for (int i = 0; i < 2; i++) {
            int o = i * 256 + tid;
            int row = o >> 2, c = o & 3;
            size_t ao = (m0 + row) * (size_t)lda + k0 + c * 8;
            size_t wo = (n0 + row) * (size_t)ldw + k0 + c * 8;
            uint32_t d = dst + row * 80 + c * 16;
            cp16(d,               Ah + ao);
            cp16(d + GT_TILE,     Al + ao);
            cp16(d + 2*GT_TILE,   Wh + wo);
            cp16(d + 3*GT_TILE,   Wl + wo);
        }
        CPC();
    };

    const int nst = K >> 5;
    load_stage(0, 0);
    load_stage(1, 1);

    const uint32_t aoff = (uint32_t)((l & 15) * 80 + (l >> 4) * 16);
    const uint32_t woff = (uint32_t)(((l & 7) + ((l >> 4) & 1) * 8) * 80
                                     + ((l >> 3) & 1) * 16);

    float acc[2][8][4];
#pragma unroll
    for (int a = 0; a < 2; a++)
#pragma unroll
        for (int b = 0; b < 8; b++)
#pragma unroll
            for (int c = 0; c < 4; c++) acc[a][b][c] = 0.0f;

    for (int s = 0; s < nst; s++) {
        const int slot = s & 1;
        if (s + 1 < nst) CPW(1);
        else             CPW(0);
        __syncthreads();

        const uint32_t stg = sb + slot * GT_STAGE;
        const uint32_t aH = stg + wm * 2560 + aoff;
        const uint32_t wH = stg + 2*GT_TILE + wn * 5120 + woff;

#pragma unroll
        for (int k16 = 0; k16 < 2; k16++) {
            uint32_t ah[2][4], al[2][4], wh[4][4], wl[4][4];
#pragma unroll
            for (int mf = 0; mf < 2; mf++) {
                ldm4(aH + mf * 1280 + k16 * 32, ah[mf]);
                ldm4(aH + GT_TILE + mf * 1280 + k16 * 32, al[mf]);
            }
#pragma unroll
            for (int g = 0; g < 4; g++) {
                ldm4(wH + g * 1280 + k16 * 32, wh[g]);
                ldm4(wH + GT_TILE + g * 1280 + k16 * 32, wl[g]);
            }
#pragma unroll
            for (int mf = 0; mf < 2; mf++)
#pragma unroll
                for (int nf = 0; nf < 8; nf++) {
                    const uint32_t* bp = wh[nf >> 1];
                    const uint32_t* lp = wl[nf >> 1];
                    uint32_t b0 = bp[(nf & 1) * 2], b1 = bp[(nf & 1) * 2 + 1];
                    uint32_t c0 = lp[(nf & 1) * 2], c1 = lp[(nf & 1) * 2 + 1];
                    mma16816(acc[mf][nf], ah[mf], b0, b1);
                    mma16816(acc[mf][nf], ah[mf], c0, c1);
                    mma16816(acc[mf][nf], al[mf], b0, b1);
                }
        }
        __syncthreads();
        if (s + 2 < nst) load_stage(slot, s + 2);
    }

    const int r0 = wm * 32 + (l >> 2);
    const int c0 = wn * 64 + (l & 3) * 2;
#pragma unroll
    for (int mf = 0; mf < 2; mf++)
#pragma unroll
        for (int nf = 0; nf < 8; nf++) {
            const long col = n0 + c0 + nf * 8;
            const float b0 = bias[col], b1 = bias[col + 1];
#pragma unroll
            for (int rr = 0; rr < 2; rr++) {
                const long row = m0 + r0 + mf * 16 + rr * 8;
                float v0 = acc[mf][nf][rr * 2]     + b0;
                float v1 = acc[mf][nf][rr * 2 + 1] + b1;
                if (ACT == 1) { v0 = act_elu(v0); v1 = act_elu(v1); }
                else if (ACT == 2) { v0 = act_softplus01(v0); v1 = act_softplus01(v1); }
                if (SPLIT) {
                    bf16 h0 = __float2bfloat16(v0);
                    bf16 h1 = __float2bfloat16(v1);
                    *(__nv_bfloat162*)&Ch[row * (long)ldc + col] =
                        __nv_bfloat162(h0, h1);
                    *(__nv_bfloat162*)&Cl[row * (long)ldc + col] = __nv_bfloat162(
                        __float2bfloat16(v0 - __bfloat162float(h0)),
                        __float2bfloat16(v1 - __bfloat162float(h1)));
                } else {
                    *(float2*)&C[row * (long)ldc + col] = make_float2(v0, v1);
                }
            }
        }
}

// =============================================================================
// step_persist v2: ALL 256 GRU timesteps, grid (48 gate-j blocks, 3 k-splits)
// = 144 CTAs. Each CTA: one 128-j tile, K split 672/672/704, A(Whh)+B(h)
// streamed per-32k-stage through a 4-deep cp.async pipeline.
// Stage slot layout: [A_hi 10240][A_lo 10240][B_hi 5120][B_lo 5120] = 30720
// =============================================================================
#define ST_ALO  10240
#define ST_BHI  20480
#define ST_BLO  25600
#define ST_SZ   30720
#define SM_P    (4 * ST_SZ)      // 122880

__global__ __launch_bounds__(256, 1) void step_persist(
    const bf16* __restrict__ whh_hi,
    const bf16* __restrict__ whh_lo,
    const bf16* __restrict__ hh0,
    const bf16* __restrict__ hl0,
    const float* __restrict__ gx,       // [T][64][6144]
    const float* __restrict__ bhh,
    float* __restrict__ ghp,            // [KSPLIT][64][6144]
    float* __restrict__ hidden,         // [T][64][2048]
    bf16* __restrict__ hhA,
    bf16* __restrict__ hlA,
    unsigned int* __restrict__ cnt)     // [2*T]
{
    extern __shared__ __align__(16) char smem[];
    const uint32_t sb = smem_u32(smem);
    const int tid = threadIdx.x;
    const int w = tid >> 5, l = tid & 31;
    const int jg0 = blockIdx.x * 128;           // global gate-row block (0..6143)
    const int ks = blockIdx.y;
    const int kbeg = ks * 672;
    const int nst  = (ks == 2) ? 22 : 21;       // 672,672,704
    const int wm = w >> 1, wn = w & 1;
    const int cta = blockIdx.y * 48 + blockIdx.x;

    // stage loaders (no commit inside)
    auto loadA = [&](int s) {
        const uint32_t dst = sb + (s & 3) * ST_SZ;
        const int k0 = kbeg + s * 32;
#pragma unroll
        for (int i = 0; i < 2; i++) {
            int o = i * 256 + tid;
            int row = o >> 2, c = o & 3;
            size_t off = (size_t)(jg0 + row) * CH_ + k0 + c * 8;
            cp16(dst + row * 80 + c * 16,          whh_hi + off);
            cp16(dst + ST_ALO + row * 80 + c * 16, whh_lo + off);
        }
    };
    auto loadB = [&](int s, const bf16* hh_in, const bf16* hl_in) {
        const uint32_t dst = sb + (s & 3) * ST_SZ;
        const int k0 = kbeg + s * 32;
        {
            int o = tid;
            int row = o >> 2, c = o & 3;
            size_t off = (size_t)row * CH_ + k0 + c * 8;
            cp16(dst + ST_BHI + row * 80 + c * 16, hh_in + off);
            cp16(dst + ST_BLO + row * 80 + c * 16, hl_in + off);
        }
    };

    // kernel-start prefetch: A0..A3 (4 groups), B0..B3 (4 groups)
#pragma unroll
    for (int i = 0; i < 4; i++) { loadA(i); CPC(); }
#pragma unroll
    for (int i = 0; i < 4; i++) { loadB(i, hh0, hl0); CPC(); }

    const uint32_t aoff = (uint32_t)((l & 15) * 80 + (l >> 4) * 16);
    const uint32_t boff = (uint32_t)(((wn * 32) + (l & 7) + ((l >> 4) & 1) * 8) * 80
                                     + ((l >> 3) & 1) * 16);

    // phase-2 per-thread constants
    const int idx4 = cta * 256 + tid;
    const bool p2 = (idx4 < B_ * CH_ / 4);
    const int pb  = idx4 >> 9;
    const int pj4 = idx4 & 511;
    float4 br4 = make_float4(0,0,0,0), bz4 = br4, bn4 = br4;
    if (p2) {
        br4 = *(const float4*)(bhh + pj4 * 4);
        bz4 = *(const float4*)(bhh + CH_ + pj4 * 4);
        bn4 = *(const float4*)(bhh + 2 * CH_ + pj4 * 4);
    }
    float4 hp = make_float4(0.f, 0.f, 0.f, 0.f);

    float acc[2][4][4];
#pragma unroll
    for (int a = 0; a < 2; a++)
#pragma unroll
        for (int b = 0; b < 4; b++)
#pragma unroll
            for (int c = 0; c < 4; c++) acc[a][b][c] = 0.0f;

    for (int t = 0; t < T_; t++) {
        const bf16* hh_cur = (t == 0) ? hh0 : hhA + (size_t)(t - 1) * HB_;
        const bf16* hl_cur = (t == 0) ? hl0 : hlA + (size_t)(t - 1) * HB_;

        // ---------------- phase 1: HMMA over this CTA's K chunk ----------------
        for (int s = 0; s < nst; s++) {
            {
                int pend = nst - 1 - s;
                if (pend >= 3)      CPW(3);
                else if (pend == 2) CPW(2);
                else if (pend == 1) CPW(1);
                else                CPW(0);
            }
            __syncthreads();

            const uint32_t stg = sb + (s & 3) * ST_SZ;
            const uint32_t aH  = stg + (uint32_t)(wm * 2560) + aoff;
            const uint32_t bH  = stg + ST_BHI + boff;
            const uint32_t bL  = stg + ST_BLO + boff;

            // hoist all fragment loads
            uint32_t ah[2][2][4], al[2][2][4], bh[2][2][4], bl[2][2][4];
#pragma unroll
            for (int k16 = 0; k16 < 2; k16++) {
#pragma unroll
                for (int mf = 0; mf < 2; mf++) {
                    ldm4(aH + mf * 1280 + k16 * 32, ah[k16][mf]);
                    ldm4(aH + ST_ALO + mf * 1280 + k16 * 32, al[k16][mf]);
                }
#pragma unroll
                for (int nf = 0; nf < 2; nf++) {
                    ldm4(bH + nf * 1280 + k16 * 32, bh[k16][nf]);
                    ldm4(bL + nf * 1280 + k16 * 32, bl[k16][nf]);
                }
            }
            __syncthreads();
            if (s + 4 < nst) { loadA(s + 4); loadB(s + 4, hh_cur, hl_cur); CPC(); }

#pragma unroll
            for (int k16 = 0; k16 < 2; k16++)
#pragma unroll
                for (int mf = 0; mf < 2; mf++)
#pragma unroll
                    for (int nf = 0; nf < 4; nf++) {
                        const uint32_t* bp = bh[k16][nf >> 1];
                        const uint32_t* lp = bl[k16][nf >> 1];
                        uint32_t b0 = bp[(nf & 1) * 2], b1 = bp[(nf & 1) * 2 + 1];
                        uint32_t c0 = lp[(nf & 1) * 2], c1 = lp[(nf & 1) * 2 + 1];
                        mma16816(acc[mf][nf], ah[k16][mf], b0, b1);
                        mma16816(acc[mf][nf], ah[k16][mf], c0, c1);
                        mma16816(acc[mf][nf], al[k16][mf], b0, b1);
                    }
        }

        // write partials + reset acc
        {
            float* base = ghp + (size_t)ks * B_ * G_;
            const int jb = jg0 + wm * 32 + (l >> 2);
            const int bb = wn * 32 + (l & 3) * 2;
#pragma unroll
            for (int mf = 0; mf < 2; mf++)
#pragma unroll
                for (int nf = 0; nf < 4; nf++) {
                    const int j = jb + mf * 16;
                    const int b = bb + nf * 8;
                    base[(size_t)b * G_ + j]           = acc[mf][nf][0];
                    base[(size_t)(b + 1) * G_ + j]     = acc[mf][nf][1];
                    base[(size_t)b * G_ + j + 8]       = acc[mf][nf][2];
                    base[(size_t)(b + 1) * G_ + j + 8] = acc[mf][nf][3];
                    acc[mf][nf][0] = acc[mf][nf][1] = 0.0f;
                    acc[mf][nf][2] = acc[mf][nf][3] = 0.0f;
                }
        }

        // ---- barrier 1; prefetch next-step A during spin ----
        __threadfence();
        __syncthreads();
        if (t + 1 < T_) {
#pragma unroll
            for (int i = 0; i < 4; i++) { loadA(i); CPC(); }
        }
        if (tid == 0) {
            unsigned v = atomicAdd(&cnt[2 * t], 1u) + 1;
            if (v < (unsigned)NCTA_STEP) {
                volatile unsigned* p = &cnt[2 * t];
                while (*p < (unsigned)NCTA_STEP) { }
            }
        }
        __syncthreads();

        // ---------------- phase 2: reduce 3 partials + gates ----------------
        if (p2) {
            const float* gx_t = gx + (size_t)t * B_ * G_;
            const long go = (long)pb * G_ + pj4 * 4;

            float4 xr = *(const float4*)(gx_t + go);
            float4 xz = *(const float4*)(gx_t + go + CH_);
            float4 xn = *(const float4*)(gx_t + go + 2*CH_);

            float4 hr = *(const float4*)(ghp + go);
            float4 hz = *(const float4*)(ghp + go + CH_);
            float4 hn = *(const float4*)(ghp + go + 2*CH_);
#pragma unroll
            for (int s = 1; s < KSPLIT; s++) {
                const float* p = ghp + (size_t)s * B_ * G_ + go;
                float4 a = *(const float4*)(p);
                float4 c = *(const float4*)(p + CH_);
                float4 d = *(const float4*)(p + 2*CH_);
                hr.x += a.x; hr.y += a.y; hr.z += a.z; hr.w += a.w;
                hz.x += c.x; hz.y += c.y; hz.z += c.z; hz.w += c.w;
                hn.x += d.x; hn.y += d.y; hn.z += d.z; hn.w += d.w;
            }
            float xrv[4] = {xr.x, xr.y, xr.z, xr.w};
            float xzv[4] = {xz.x, xz.y, xz.z, xz.w};
            float xnv[4] = {xn.x, xn.y, xn.z, xn.w};
            float hrv[4] = {hr.x + br4.x, hr.y + br4.y, hr.z + br4.z, hr.w + br4.w};
            float hzv[4] = {hz.x + bz4.x, hz.y + bz4.y, hz.z + bz4.z, hz.w + bz4.w};
            float hnv[4] = {hn.x + bn4.x, hn.y + bn4.y, hn.z + bn4.z, hn.w + bn4.w};
            float hpv[4] = {hp.x, hp.y, hp.z, hp.w};
            float ov[4];
#pragma unroll
            for (int i = 0; i < 4; i++) {
                float r = 1.0f / (1.0f + expf(-(xrv[i] + hrv[i])));
                float z = 1.0f / (1.0f + expf(-(xzv[i] + hzv[i])));
                float n = tanhf(xnv[i] + r * hnv[i]);
                ov[i] = (1.0f - z) * n + z * hpv[i];
            }
            hp = make_float4(ov[0], ov[1], ov[2], ov[3]);

            const long ho = (long)pb * CH_ + pj4 * 4;
            *(float4*)(hidden + (size_t)t * HB_ + ho) = hp;
            bf16* hhp = hhA + (size_t)t * HB_ + ho;
            bf16* hlp = hlA + (size_t)t * HB_ + ho;
#pragma unroll
            for (int i = 0; i < 4; i++) {
                bf16 hi = __float2bfloat16(ov[i]);
                hhp[i] = hi;
                hlp[i] = __float2bfloat16(ov[i] - __bfloat162float(hi));
            }
        }

        // ---- barrier 2 (h(t) visible) ----
        __threadfence();
        __syncthreads();
        if (tid == 0) {
            unsigned v = atomicAdd(&cnt[2 * t + 1], 1u) + 1;
            if (v < (unsigned)NCTA_STEP) {
                volatile unsigned* p = &cnt[2 * t + 1];
                while (*p < (unsigned)NCTA_STEP) { }
            }
        }
        __syncthreads();

        // load next-step B stages 0..3 (h(t) just produced)
        if (t + 1 < T_) {
            const bf16* nh = hhA + (size_t)t * HB_;
            const bf16* nl = hlA + (size_t)t * HB_;
#pragma unroll
            for (int i = 0; i < 4; i++) { loadB(i, nh, nl); CPC(); }
        }
    }
}

// =============================================================================
extern "C" void kernel_launch(void* const* d_in, const int* in_sizes, int n_in,
                              void* d_out, int out_size)
{
    const float* x    = (const float*)d_in[0];
    const float* We   = (const float*)d_in[1];
    const float* be   = (const float*)d_in[2];
    const float* Wih  = (const float*)d_in[3];
    const float* bih  = (const float*)d_in[4];
    const float* Whh  = (const float*)d_in[5];
    const float* bhh  = (const float*)d_in[6];
    const float* Wmu  = (const float*)d_in[7];
    const float* bmu  = (const float*)d_in[8];
    const float* Wsig = (const float*)d_in[9];
    const float* bsig = (const float*)d_in[10];

    float* out        = (float*)d_out;
    float* out_mu     = out;
    float* out_sig    = out + (size_t)MB_ * DOUT_;
    float* out_hidden = out + (size_t)2 * MB_ * DOUT_;

    float *p_gx, *p_ghp;
    bf16 *p_xh, *p_xl, *p_xeh, *p_xel, *p_weh, *p_wel, *p_wihh, *p_wihl;
    bf16 *p_whhh, *p_whhl, *p_wmuh, *p_wmul, *p_wsgh, *p_wsgl;
    bf16 *p_hhA, *p_hlA, *p_hh0, *p_hl0;
    unsigned int* p_cnt;
    cudaGetSymbolAddress((void**)&p_gx, g_gx);
    cudaGetSymbolAddress((void**)&p_ghp, g_ghp);
    cudaGetSymbolAddress((void**)&p_xh, g_xh);
    cudaGetSymbolAddress((void**)&p_xl, g_xl);
    cudaGetSymbolAddress((void**)&p_xeh, g_xeh);
    cudaGetSymbolAddress((void**)&p_xel, g_xel);
    cudaGetSymbolAddress((void**)&p_weh, g_weh);
    cudaGetSymbolAddress((void**)&p_wel, g_wel);
    cudaGetSymbolAddress((void**)&p_wihh, g_wihh);
    cudaGetSymbolAddress((void**)&p_wihl, g_wihl);
    cudaGetSymbolAddress((void**)&p_whhh, g_whh_hi);
    cudaGetSymbolAddress((void**)&p_whhl, g_whh_lo);
    cudaGetSymbolAddress((void**)&p_wmuh, g_wmuh);
    cudaGetSymbolAddress((void**)&p_wmul, g_wmul);
    cudaGetSymbolAddress((void**)&p_wsgh, g_wsgh);
    cudaGetSymbolAddress((void**)&p_wsgl, g_wsgl);
    cudaGetSymbolAddress((void**)&p_hhA, g_hhA);
    cudaGetSymbolAddress((void**)&p_hlA, g_hlA);
    cudaGetSymbolAddress((void**)&p_hh0, g_hh0);
    cudaGetSymbolAddress((void**)&p_hl0, g_hl0);
    cudaGetSymbolAddress((void**)&p_cnt, g_cnt);

    cudaFuncSetAttribute(step_persist, cudaFuncAttributeMaxDynamicSharedMemorySize, SM_P);
    cudaFuncSetAttribute(gemm_tc<0,0>, cudaFuncAttributeMaxDynamicSharedMemorySize, GT_SMEM);
    cudaFuncSetAttribute(gemm_tc<1,0>, cudaFuncAttributeMaxDynamicSharedMemorySize, GT_SMEM);
    cudaFuncSetAttribute(gemm_tc<2,0>, cudaFuncAttributeMaxDynamicSharedMemorySize, GT_SMEM);
    cudaFuncSetAttribute(gemm_tc<1,1>, cudaFuncAttributeMaxDynamicSharedMemorySize, GT_SMEM);

    dim3 blk(256);
    init_kernel<<<512, blk>>>();
    split_f2b<<<(int)((size_t)MB_ * DIN_ / 1024), blk>>>(x, p_xh, p_xl);
    split_f2b<<<(int)((size_t)H_ * DIN_ / 1024), blk>>>(We, p_weh, p_wel);
    split_f2b<<<(int)((size_t)G_ * H_ / 1024), blk>>>(Wih, p_wihh, p_wihl);
    split_f2b<<<(int)((size_t)G_ * CH_ / 1024), blk>>>(Whh, p_whhh, p_whhl);
    split_f2b<<<(int)((size_t)DOUT_ * H_ / 1024), blk>>>(Wmu, p_wmuh, p_wmul);
    split_f2b<<<(int)((size_t)DOUT_ * H_ / 1024), blk>>>(Wsig, p_wsgh, p_wsgl);

    // enc: xe = elu(x @ We^T + be) -> bf16 hi/lo, K=512 (ldc = H_)
    gemm_tc<1,1><<<dim3(H_/128, MB_/128), blk, GT_SMEM>>>(
        p_xh, p_xl, DIN_, p_weh, p_wel, DIN_, be,
        nullptr, H_, p_xeh, p_xel, DIN_);
    // gx = xe @ Wih^T + bih (fp32), K=1024
    gemm_tc<0,0><<<dim3(G_/128, MB_/128), blk, GT_SMEM>>>(
        p_xeh, p_xel, H_, p_wihh, p_wihl, H_, bih,
        p_gx, G_, nullptr, nullptr, H_);

    // recurrence: ONE persistent kernel, 144 CTAs
    step_persist<<<dim3(48, KSPLIT), blk, SM_P>>>(
        p_whhh, p_whhl, p_hh0, p_hl0, p_gx, bhh, p_ghp,
        out_hidden, p_hhA, p_hlA, p_cnt);

    // heads (K=1024)
    gemm_tc<1,0><<<dim3(DOUT_/128, MB_/128), blk, GT_SMEM>>>(
        p_hhA, p_hlA, CH_, p_wmuh, p_wmul, H_, bmu,
        out_mu, DOUT_, nullptr, nullptr, H_);
    gemm_tc<2,0><<<dim3(DOUT_/128, MB_/128), blk, GT_SMEM>>>(
        p_hhA + H_, p_hlA + H_, CH_, p_wsgh, p_wsgl, H_, bsig,
        out_sig, DOUT_, nullptr, nullptr, H_);
}